// round 2
// baseline (speedup 1.0000x reference)
#include <cuda_runtime.h>
#include <cuda_bf16.h>
#include <math.h>

// Problem constants (fixed shapes)
#define N_SPOTS 10000
#define D_LAT   128
#define D_IN    3000
#define KNN_K   10
#define SCALE   6
#define BN_EPS  1e-4f

#define INF_F __int_as_float(0x7f800000)

// ---------------- scratch (device globals; no allocation allowed) -------------
__device__ int   g_idx[N_SPOTS * KNN_K];
__device__ float g_h[(size_t)N_SPOTS * D_IN];           // 120 MB GEMM output
__device__ float g_ps [32 * D_IN];                      // partial sums
__device__ float g_pss[32 * D_IN];                      // partial sumsq
__device__ float g_mu[D_IN];
__device__ float g_rs[D_IN];

// lexicographic (d2, idx) compare: matches jax.lax.top_k stable tie-break
__device__ __forceinline__ bool lexless(float d1, int j1, float d2, int j2) {
    return (d1 < d2) || (d1 == d2 && j1 < j2);
}

// ------------------------------- KNN ------------------------------------------
// One block per query row i. 256 threads scan candidates j = tid, tid+256, ...
// Each thread keeps a local top-10 (replace-worst). Then 10 rounds of
// block-wide lexicographic argmin merge.
//
// d2 must be BIT-EXACT vs reference. XLA rewrites the K=2 dot into
// multiply + 2-element reduce (NO fma):
//   sq_j = rn(rn(x*x) + rn(y*y))
//   dot  = rn(rn(x_i*x_j) + rn(y_i*y_j))
//   d2   = rn(rn(sq_i + sq_j) - 2*dot)            (2*dot exact)
__global__ void knn_kernel(const float2* __restrict__ sp, int* __restrict__ idx_out) {
    const int i   = blockIdx.x;
    const int tid = threadIdx.x;

    const float2 si  = __ldg(&sp[i]);
    const float  sqi = __fadd_rn(__fmul_rn(si.x, si.x), __fmul_rn(si.y, si.y));

    float dd[KNN_K];
    int   jj[KNN_K];
#pragma unroll
    for (int k = 0; k < KNN_K; k++) { dd[k] = INF_F; jj[k] = 0x7fffffff; }
    float wd = INF_F; int wj = 0x7fffffff; int ws = 0;

    for (int j = tid; j < N_SPOTS; j += 256) {
        if (j == i) continue;
        const float2 s   = __ldg(&sp[j]);
        const float  sqj = __fadd_rn(__fmul_rn(s.x, s.x), __fmul_rn(s.y, s.y));
        const float  dot = __fadd_rn(__fmul_rn(si.x, s.x), __fmul_rn(si.y, s.y));
        const float  d2  = __fadd_rn(__fadd_rn(sqi, sqj), __fmul_rn(-2.0f, dot));
        if (lexless(d2, j, wd, wj)) {
            // replace worst slot
#pragma unroll
            for (int k = 0; k < KNN_K; k++) if (k == ws) { dd[k] = d2; jj[k] = j; }
            // recompute worst (lexicographic max)
            wd = dd[0]; wj = jj[0]; ws = 0;
#pragma unroll
            for (int k = 1; k < KNN_K; k++)
                if (lexless(wd, wj, dd[k], jj[k])) { wd = dd[k]; wj = jj[k]; ws = k; }
        }
    }

    // ---- merge: 10 rounds of block argmin over per-thread survivors ----
    __shared__ float rd[256];
    __shared__ int   rj[256];
    __shared__ int   ro[256];

    for (int r = 0; r < KNN_K; r++) {
        float ld = INF_F; int lj = 0x7fffffff; int ls = -1;
#pragma unroll
        for (int k = 0; k < KNN_K; k++)
            if (lexless(dd[k], jj[k], ld, lj)) { ld = dd[k]; lj = jj[k]; ls = k; }
        rd[tid] = ld; rj[tid] = lj; ro[tid] = tid;
        __syncthreads();
        for (int s = 128; s > 0; s >>= 1) {
            if (tid < s) {
                if (lexless(rd[tid + s], rj[tid + s], rd[tid], rj[tid])) {
                    rd[tid] = rd[tid + s]; rj[tid] = rj[tid + s]; ro[tid] = ro[tid + s];
                }
            }
            __syncthreads();
        }
        if (tid == 0) idx_out[i * KNN_K + r] = rj[0];
        if (tid == ro[0]) {
#pragma unroll
            for (int k = 0; k < KNN_K; k++) if (k == ls) { dd[k] = INF_F; jj[k] = 0x7fffffff; }
        }
        __syncthreads();
    }
}

// --------------------------- aggregation --------------------------------------
// One block (128 threads = one per latent dim) per row i.
//   w_k = softmax_k( -mean_d (x[nbr_k,d]-x[i,d])^2 )
//   z_lr[i,:]  = sum_k w_k * x[nbr_k,:]
//   x1_hr[i, s*128+d] = sum_k w_k * x_neighbor[s*N + nbr_k, d]
__global__ void agg_kernel(const float* __restrict__ x,
                           const float* __restrict__ xn,
                           float* __restrict__ z_out,
                           float* __restrict__ hr_out) {
    const int i   = blockIdx.x;
    const int tid = threadIdx.x;          // 0..127
    const int lane = tid & 31, wrp = tid >> 5;

    __shared__ int   nb[KNN_K];
    __shared__ float red[4][KNN_K];
    __shared__ float neg_mean[KNN_K];

    if (tid < KNN_K) nb[tid] = g_idx[i * KNN_K + tid];
    __syncthreads();

    const float xi = x[(size_t)i * D_LAT + tid];
    float xv[KNN_K];
    float fd[KNN_K];
#pragma unroll
    for (int k = 0; k < KNN_K; k++) {
        const float v = x[(size_t)nb[k] * D_LAT + tid];
        xv[k] = v;
        const float d = v - xi;
        fd[k] = d * d;
    }
    // reduce fd[k] over 128 threads
#pragma unroll
    for (int k = 0; k < KNN_K; k++) {
        float v = fd[k];
#pragma unroll
        for (int o = 16; o > 0; o >>= 1) v += __shfl_xor_sync(0xffffffffu, v, o);
        if (lane == 0) red[wrp][k] = v;
    }
    __syncthreads();
    if (tid < KNN_K) {
        const float s = red[0][tid] + red[1][tid] + red[2][tid] + red[3][tid];
        neg_mean[tid] = -(s * (1.0f / 128.0f));
    }
    __syncthreads();

    // softmax over 10 values (computed redundantly in every thread)
    float m = neg_mean[0];
#pragma unroll
    for (int k = 1; k < KNN_K; k++) m = fmaxf(m, neg_mean[k]);
    float e[KNN_K], se = 0.0f;
#pragma unroll
    for (int k = 0; k < KNN_K; k++) { e[k] = expf(neg_mean[k] - m); se += e[k]; }
    float w[KNN_K];
#pragma unroll
    for (int k = 0; k < KNN_K; k++) w[k] = e[k] / se;

    // z_lr
    float acc = 0.0f;
#pragma unroll
    for (int k = 0; k < KNN_K; k++) acc = __fmaf_rn(w[k], xv[k], acc);
    z_out[(size_t)i * D_LAT + tid] = acc;

    // x1_hr: xn[(s*N + nbr)*128 + d]
#pragma unroll
    for (int s = 0; s < SCALE; s++) {
        float a = 0.0f;
#pragma unroll
        for (int k = 0; k < KNN_K; k++)
            a = __fmaf_rn(w[k], xn[((size_t)s * N_SPOTS + nb[k]) * D_LAT + tid], a);
        hr_out[(size_t)i * (SCALE * D_LAT) + s * D_LAT + tid] = a;
    }
}

// ------------------------------ GEMM -------------------------------------------
// h = z_lr @ W + b    [10000 x 3000], K = 128.  128x128 block tile, 8x8/thread.
#define GM 128
#define GN 128
#define GK 8
__global__ void __launch_bounds__(256) gemm_kernel(const float* __restrict__ A,
                                                   const float* __restrict__ B,
                                                   const float* __restrict__ bias) {
    __shared__ float As[GK][GM];
    __shared__ float Bs[GK][GN];
    const int bm  = blockIdx.y * GM;
    const int bn  = blockIdx.x * GN;
    const int tid = threadIdx.x;
    const int tx  = tid & 15, ty = tid >> 4;

    float acc[8][8];
#pragma unroll
    for (int p = 0; p < 8; p++)
#pragma unroll
        for (int q = 0; q < 8; q++) acc[p][q] = 0.0f;

    for (int k0 = 0; k0 < D_LAT; k0 += GK) {
#pragma unroll
        for (int r = 0; r < 4; r++) {
            const int e = tid + 256 * r;
            const int m = e >> 3, k = e & 7;
            const int gm = bm + m;
            As[k][m] = (gm < N_SPOTS) ? A[(size_t)gm * D_LAT + k0 + k] : 0.0f;
        }
#pragma unroll
        for (int r = 0; r < 4; r++) {
            const int e = tid + 256 * r;
            const int k = e >> 7, n = e & 127;
            const int gn = bn + n;
            Bs[k][n] = (gn < D_IN) ? B[(size_t)(k0 + k) * D_IN + gn] : 0.0f;
        }
        __syncthreads();
#pragma unroll
        for (int kk = 0; kk < GK; kk++) {
            float a[8], b[8];
#pragma unroll
            for (int u = 0; u < 8; u++) a[u] = As[kk][ty * 8 + u];
#pragma unroll
            for (int u = 0; u < 8; u++) b[u] = Bs[kk][tx * 8 + u];
#pragma unroll
            for (int p = 0; p < 8; p++)
#pragma unroll
                for (int q = 0; q < 8; q++)
                    acc[p][q] = __fmaf_rn(a[p], b[q], acc[p][q]);
        }
        __syncthreads();
    }

#pragma unroll
    for (int p = 0; p < 8; p++) {
        const int gm = bm + ty * 8 + p;
        if (gm < N_SPOTS) {
#pragma unroll
            for (int q = 0; q < 8; q++) {
                const int gn = bn + tx * 8 + q;
                if (gn < D_IN)
                    g_h[(size_t)gm * D_IN + gn] = acc[p][q] + __ldg(&bias[gn]);
            }
        }
    }
}

// -------------------------- batch-norm statistics ------------------------------
#define ROW_SLICES 32
#define ROWS_PER_SLICE 313   // 32*313 = 10016 >= 10000

__global__ void stats1_kernel() {
    const int c = blockIdx.x * 128 + threadIdx.x;
    const int slice = blockIdx.y;
    if (c >= D_IN) return;
    const int r0 = slice * ROWS_PER_SLICE;
    const int r1 = min(r0 + ROWS_PER_SLICE, N_SPOTS);
    float s = 0.0f, ss = 0.0f;
    for (int r = r0; r < r1; r++) {
        const float v = g_h[(size_t)r * D_IN + c];
        s += v;
        ss = __fmaf_rn(v, v, ss);
    }
    g_ps [slice * D_IN + c] = s;
    g_pss[slice * D_IN + c] = ss;
}

__global__ void stats2_kernel() {
    const int c = blockIdx.x * 128 + threadIdx.x;
    if (c >= D_IN) return;
    float s = 0.0f, ss = 0.0f;
    for (int p = 0; p < ROW_SLICES; p++) { s += g_ps[p * D_IN + c]; ss += g_pss[p * D_IN + c]; }
    const float mu  = s * (1.0f / (float)N_SPOTS);
    const float var = ss * (1.0f / (float)N_SPOTS) - mu * mu;
    g_mu[c] = mu;
    g_rs[c] = 1.0f / sqrtf(var + BN_EPS);
}

// ----------------------------- BN + ELU ----------------------------------------
__global__ void bnelu_kernel(const float* __restrict__ gamma,
                             const float* __restrict__ beta,
                             float* __restrict__ out) {
    const int r = blockIdx.x;
    for (int c = threadIdx.x; c < D_IN; c += blockDim.x) {
        const float v = g_h[(size_t)r * D_IN + c];
        float y = (v - g_mu[c]) * g_rs[c];
        y = y * __ldg(&gamma[c]) + __ldg(&beta[c]);
        out[(size_t)r * D_IN + c] = (y > 0.0f) ? y : expm1f(y);
    }
}

// ------------------------------- launch ----------------------------------------
extern "C" void kernel_launch(void* const* d_in, const int* in_sizes, int n_in,
                              void* d_out, int out_size) {
    const float* x     = (const float*)d_in[0];   // [10000,128]
    const float* xn    = (const float*)d_in[1];   // [60000,128]
    const float* sp    = (const float*)d_in[2];   // [10000,2]
    const float* W     = (const float*)d_in[3];   // [128,3000]
    const float* bias  = (const float*)d_in[4];   // [3000]
    const float* gamma = (const float*)d_in[5];   // [3000]
    const float* beta  = (const float*)d_in[6];   // [3000]

    float* out = (float*)d_out;
    float* z_out  = out;                                   // [10000,128]
    float* de_out = out + (size_t)N_SPOTS * D_LAT;         // [10000,3000]
    float* hr_out = de_out + (size_t)N_SPOTS * D_IN;       // [10000,768]

    // device-global symbol addresses are referenced inside kernels directly
    int* idx_ptr;
    cudaGetSymbolAddress((void**)&idx_ptr, g_idx);

    knn_kernel<<<N_SPOTS, 256>>>((const float2*)sp, idx_ptr);
    agg_kernel<<<N_SPOTS, 128>>>(x, xn, z_out, hr_out);
    gemm_kernel<<<dim3((D_IN + GN - 1) / GN, (N_SPOTS + GM - 1) / GM), 256>>>(z_out, W, bias);
    stats1_kernel<<<dim3((D_IN + 127) / 128, ROW_SLICES), 128>>>();
    stats2_kernel<<<(D_IN + 127) / 128, 128>>>();
    bnelu_kernel<<<N_SPOTS, 256>>>(gamma, beta, de_out);
}

// round 3
// speedup vs baseline: 2.7005x; 2.7005x over previous
#include <cuda_runtime.h>
#include <cuda_bf16.h>
#include <math.h>

// Problem constants (fixed shapes)
#define N_SPOTS 10000
#define D_LAT   128
#define D_IN    3000
#define KNN_K   10
#define SCALE   6
#define BN_EPS  1e-4f

// KNN grid
#define GRID_D  40
#define CSZ     2.5f
#define INV_CSZ 0.4f
#define NCELLS  (GRID_D * GRID_D)
#define SLACK   0.5f

#define INF_F __int_as_float(0x7f800000)

// ---------------- scratch (device globals; no allocation allowed) -------------
__device__ int    g_idx[N_SPOTS * KNN_K];
__device__ __align__(16) float g_h[(size_t)N_SPOTS * D_IN];   // 120 MB GEMM output
__device__ int    g_cnt[NCELLS];
__device__ int    g_cur[NCELLS];
__device__ int    g_startc[NCELLS];
__device__ __align__(16) float2 g_sx[N_SPOTS];
__device__ int    g_si[N_SPOTS];
__device__ __align__(16) float g_sum[D_IN];
__device__ __align__(16) float g_sumsq[D_IN];
__device__ __align__(16) float g_mu[D_IN];
__device__ __align__(16) float g_rs[D_IN];

// lexicographic (d2, idx) compare: matches jax.lax.top_k stable tie-break
__device__ __forceinline__ bool lexless(float d1, int j1, float d2, int j2) {
    return (d1 < d2) || (d1 == d2 && j1 < j2);
}

__device__ __forceinline__ int cell_x(float x) {
    int c = (int)(x * INV_CSZ);
    return min(GRID_D - 1, max(0, c));
}

// ----------------------------- KNN: build grid ---------------------------------
__global__ void knn_count(const float2* __restrict__ sp) {
    const int i = blockIdx.x * 256 + threadIdx.x;
    if (i >= N_SPOTS) return;
    const float2 s = sp[i];
    atomicAdd(&g_cnt[cell_x(s.y) * GRID_D + cell_x(s.x)], 1);
}

// single-warp exclusive scan over 1600 cells
__global__ void knn_scan() {
    const int lane = threadIdx.x;           // 32 threads
    const int CH = NCELLS / 32;             // 50
    const int base = lane * CH;
    int s = 0;
    for (int k = 0; k < CH; k++) s += g_cnt[base + k];
    int inc = s;
#pragma unroll
    for (int o = 1; o < 32; o <<= 1) {
        int v = __shfl_up_sync(0xffffffffu, inc, o);
        if (lane >= o) inc += v;
    }
    int run = inc - s;                      // exclusive prefix of this chunk
    for (int k = 0; k < CH; k++) {
        const int c = g_cnt[base + k];
        g_startc[base + k] = run;
        run += c;
    }
}

__global__ void knn_scatter(const float2* __restrict__ sp) {
    const int i = blockIdx.x * 256 + threadIdx.x;
    if (i >= N_SPOTS) return;
    const float2 s = sp[i];
    const int c = cell_x(s.y) * GRID_D + cell_x(s.x);
    const int dst = g_startc[c] + atomicAdd(&g_cur[c], 1);
    g_sx[dst] = s;
    g_si[dst] = i;
}

// ----------------------------- KNN: ring search --------------------------------
// d2 must be BIT-EXACT vs reference (XLA lowers the K=2 dot without fma):
//   sq = rn(rn(x*x) + rn(y*y));  dot = rn(rn(xi*xj) + rn(yi*yj))
//   d2 = rn(rn(sqi + sqj) - 2*dot)
__device__ __forceinline__ void proc_cell(int c, int i, float mx, float my, float sqi,
                                          float* dd, int* jj,
                                          float& wd, int& wj, int& ws) {
    const int t0 = g_startc[c];
    const int t1 = t0 + g_cnt[c];
    for (int t = t0; t < t1; t++) {
        const int j = g_si[t];
        const float2 s = g_sx[t];
        if (j == i) continue;
        const float sqj = __fadd_rn(__fmul_rn(s.x, s.x), __fmul_rn(s.y, s.y));
        const float dot = __fadd_rn(__fmul_rn(mx, s.x), __fmul_rn(my, s.y));
        const float d2  = __fadd_rn(__fadd_rn(sqi, sqj), __fmul_rn(-2.0f, dot));
        if (lexless(d2, j, wd, wj)) {
#pragma unroll
            for (int k = 0; k < KNN_K; k++) if (k == ws) { dd[k] = d2; jj[k] = j; }
            wd = dd[0]; wj = jj[0]; ws = 0;
#pragma unroll
            for (int k = 1; k < KNN_K; k++)
                if (lexless(wd, wj, dd[k], jj[k])) { wd = dd[k]; wj = jj[k]; ws = k; }
        }
    }
}

__global__ void knn_search(int* __restrict__ idx_out) {
    const int p = blockIdx.x * 128 + threadIdx.x;   // sorted position (cell-local warps)
    if (p >= N_SPOTS) return;
    const float2 me = g_sx[p];
    const int i = g_si[p];
    const float sqi = __fadd_rn(__fmul_rn(me.x, me.x), __fmul_rn(me.y, me.y));
    const int cx = cell_x(me.x), cy = cell_x(me.y);

    float dd[KNN_K]; int jj[KNN_K];
#pragma unroll
    for (int k = 0; k < KNN_K; k++) { dd[k] = INF_F; jj[k] = 0x7fffffff; }
    float wd = INF_F; int wj = 0x7fffffff; int ws = 0;

    for (int R = 0; R <= GRID_D; R++) {
        if (R >= 2) {
            // unprocessed cells have Chebyshev >= R -> true d >= (R-1)*CSZ.
            // computed d2 >= true d2 - eps(~0.02) ; SLACK=0.5 covers eps.
            const float b = (float)(R - 1) * CSZ;
            if (wd + SLACK < b * b) break;   // wd==INF while <10 found -> no break
        }
        const int x0 = max(0, cx - R), x1 = min(GRID_D - 1, cx + R);
        const int y0 = max(0, cy - R), y1 = min(GRID_D - 1, cy + R);
        for (int yy = y0; yy <= y1; yy++) {
            if (yy == cy - R || yy == cy + R) {
                for (int xx = x0; xx <= x1; xx++)
                    proc_cell(yy * GRID_D + xx, i, me.x, me.y, sqi, dd, jj, wd, wj, ws);
            } else {
                if (cx - R >= 0)     proc_cell(yy * GRID_D + cx - R, i, me.x, me.y, sqi, dd, jj, wd, wj, ws);
                if (cx + R < GRID_D) proc_cell(yy * GRID_D + cx + R, i, me.x, me.y, sqi, dd, jj, wd, wj, ws);
            }
        }
    }
#pragma unroll
    for (int k = 0; k < KNN_K; k++) idx_out[i * KNN_K + k] = jj[k];
}

// --------------------------- aggregation --------------------------------------
__global__ void agg_kernel(const float* __restrict__ x,
                           const float* __restrict__ xn,
                           float* __restrict__ z_out,
                           float* __restrict__ hr_out) {
    const int i   = blockIdx.x;
    const int tid = threadIdx.x;          // 0..127
    const int lane = tid & 31, wrp = tid >> 5;

    __shared__ int   nb[KNN_K];
    __shared__ float red[4][KNN_K];
    __shared__ float neg_mean[KNN_K];

    if (tid < KNN_K) nb[tid] = g_idx[i * KNN_K + tid];
    __syncthreads();

    const float xi = x[(size_t)i * D_LAT + tid];
    float xv[KNN_K];
    float fd[KNN_K];
#pragma unroll
    for (int k = 0; k < KNN_K; k++) {
        const float v = x[(size_t)nb[k] * D_LAT + tid];
        xv[k] = v;
        const float d = v - xi;
        fd[k] = d * d;
    }
#pragma unroll
    for (int k = 0; k < KNN_K; k++) {
        float v = fd[k];
#pragma unroll
        for (int o = 16; o > 0; o >>= 1) v += __shfl_xor_sync(0xffffffffu, v, o);
        if (lane == 0) red[wrp][k] = v;
    }
    __syncthreads();
    if (tid < KNN_K) {
        const float s = red[0][tid] + red[1][tid] + red[2][tid] + red[3][tid];
        neg_mean[tid] = -(s * (1.0f / 128.0f));
    }
    __syncthreads();

    float m = neg_mean[0];
#pragma unroll
    for (int k = 1; k < KNN_K; k++) m = fmaxf(m, neg_mean[k]);
    float e[KNN_K], se = 0.0f;
#pragma unroll
    for (int k = 0; k < KNN_K; k++) { e[k] = expf(neg_mean[k] - m); se += e[k]; }
    float w[KNN_K];
#pragma unroll
    for (int k = 0; k < KNN_K; k++) w[k] = e[k] / se;

    float acc = 0.0f;
#pragma unroll
    for (int k = 0; k < KNN_K; k++) acc = __fmaf_rn(w[k], xv[k], acc);
    z_out[(size_t)i * D_LAT + tid] = acc;

#pragma unroll
    for (int s = 0; s < SCALE; s++) {
        float a = 0.0f;
#pragma unroll
        for (int k = 0; k < KNN_K; k++)
            a = __fmaf_rn(w[k], xn[((size_t)s * N_SPOTS + nb[k]) * D_LAT + tid], a);
        hr_out[(size_t)i * (SCALE * D_LAT) + s * D_LAT + tid] = a;
    }
}

// ------------------------------ GEMM -------------------------------------------
// h = z_lr @ W + b  [10000 x 3000], K=128. 128x128 tile, TK=16, double-buffered.
// Fused: bias add, store h, per-column sum/sumsq atomics (BN stats).
#define GM 128
#define GN 128
#define GK 16

__global__ void __launch_bounds__(256) gemm_kernel(const float* __restrict__ A,
                                                   const float* __restrict__ B,
                                                   const float* __restrict__ bias) {
    __shared__ float As[2][GK][GM];
    __shared__ float Bs[2][GK][GN];
    const int bm  = blockIdx.y * GM;
    const int bn  = blockIdx.x * GN;
    const int tid = threadIdx.x;
    const int tx  = tid & 15, ty = tid >> 4;

    // A: row ar (0..127), k-quad pair aq (0..1): loads k = aq*8 + {0..3, 4..7}
    const int ar = tid & 127;
    const int aq = tid >> 7;
    // B: k row bk (0..7) per half, columns bn4*4
    const int bk  = tid >> 5;
    const int bn4 = (tid & 31) * 4;

    const int arow = min(bm + ar, N_SPOTS - 1);
    const int bcol = min(bn + bn4, D_IN - 4);
    const float4* A4 = (const float4*)(A + (size_t)arow * D_LAT);

    float4 ra0, ra1, rb0, rb1;
    ra0 = A4[aq * 2];
    ra1 = A4[aq * 2 + 1];
    rb0 = *(const float4*)(B + (size_t)bk * D_IN + bcol);
    rb1 = *(const float4*)(B + (size_t)(bk + 8) * D_IN + bcol);

    float acc[8][8];
#pragma unroll
    for (int p = 0; p < 8; p++)
#pragma unroll
        for (int q = 0; q < 8; q++) acc[p][q] = 0.0f;

#define STS_AB(buf)                                                          \
    {                                                                        \
        As[buf][aq * 8 + 0][ar] = ra0.x; As[buf][aq * 8 + 1][ar] = ra0.y;    \
        As[buf][aq * 8 + 2][ar] = ra0.z; As[buf][aq * 8 + 3][ar] = ra0.w;    \
        As[buf][aq * 8 + 4][ar] = ra1.x; As[buf][aq * 8 + 5][ar] = ra1.y;    \
        As[buf][aq * 8 + 6][ar] = ra1.z; As[buf][aq * 8 + 7][ar] = ra1.w;    \
        *(float4*)&Bs[buf][bk][bn4 & 127]     = rb0;                         \
        *(float4*)&Bs[buf][bk + 8][bn4 & 127] = rb1;                         \
    }

    STS_AB(0);
    __syncthreads();

#pragma unroll
    for (int s = 0; s < 8; s++) {
        if (s < 7) {
            const int k0 = (s + 1) * GK;
            ra0 = A4[(s + 1) * 4 + aq * 2];
            ra1 = A4[(s + 1) * 4 + aq * 2 + 1];
            rb0 = *(const float4*)(B + (size_t)(k0 + bk) * D_IN + bcol);
            rb1 = *(const float4*)(B + (size_t)(k0 + bk + 8) * D_IN + bcol);
        }
        const int cur = s & 1;
#pragma unroll
        for (int kk = 0; kk < GK; kk++) {
            float a[8], b[8];
            *(float4*)&a[0] = *(const float4*)&As[cur][kk][ty * 8];
            *(float4*)&a[4] = *(const float4*)&As[cur][kk][ty * 8 + 4];
            *(float4*)&b[0] = *(const float4*)&Bs[cur][kk][tx * 8];
            *(float4*)&b[4] = *(const float4*)&Bs[cur][kk][tx * 8 + 4];
#pragma unroll
            for (int p = 0; p < 8; p++)
#pragma unroll
                for (int q = 0; q < 8; q++)
                    acc[p][q] = __fmaf_rn(a[p], b[q], acc[p][q]);
        }
        if (s < 7) {
            STS_AB((s + 1) & 1);
            __syncthreads();
        }
    }

    // epilogue: bias, store h, column sums (only valid rows/cols contribute)
    float4 bias0 = *(const float4*)(bias + min(bn + tx * 8,     D_IN - 4));
    float4 bias1 = *(const float4*)(bias + min(bn + tx * 8 + 4, D_IN - 4));
    const float bq[8] = {bias0.x, bias0.y, bias0.z, bias0.w,
                         bias1.x, bias1.y, bias1.z, bias1.w};

#pragma unroll
    for (int p = 0; p < 8; p++) {
        const int gm = bm + ty * 8 + p;
        if (gm >= N_SPOTS) continue;
        float h[8];
#pragma unroll
        for (int q = 0; q < 8; q++) h[q] = acc[p][q] + bq[q];
        float* dst = g_h + (size_t)gm * D_IN + bn + tx * 8;
        if (bn + tx * 8 + 3 < D_IN)     *(float4*)dst       = *(float4*)&h[0];
        if (bn + tx * 8 + 7 < D_IN)     *(float4*)(dst + 4) = *(float4*)&h[4];
    }
#pragma unroll
    for (int q = 0; q < 8; q++) {
        const int gn = bn + tx * 8 + q;
        if (gn >= D_IN) continue;
        float s = 0.0f, ss = 0.0f;
#pragma unroll
        for (int p = 0; p < 8; p++) {
            if (bm + ty * 8 + p < N_SPOTS) {
                const float h = acc[p][q] + bq[q];
                s += h;
                ss = __fmaf_rn(h, h, ss);
            }
        }
        atomicAdd(&g_sum[gn], s);
        atomicAdd(&g_sumsq[gn], ss);
    }
}

// -------------------------- finalize BN statistics ------------------------------
__global__ void stats2_kernel() {
    const int c = blockIdx.x * 128 + threadIdx.x;
    if (c >= D_IN) return;
    const float mu  = g_sum[c]   * (1.0f / (float)N_SPOTS);
    const float var = g_sumsq[c] * (1.0f / (float)N_SPOTS) - mu * mu;
    g_mu[c] = mu;
    g_rs[c] = 1.0f / sqrtf(var + BN_EPS);
}

// ----------------------------- BN + ELU ----------------------------------------
__global__ void bnelu_kernel(const float* __restrict__ gamma,
                             const float* __restrict__ beta,
                             float* __restrict__ out) {
    const int r = blockIdx.x;
    const float4* hrow = (const float4*)(g_h + (size_t)r * D_IN);
    float4* orow = (float4*)(out + (size_t)r * D_IN);
    const float4* mu4 = (const float4*)g_mu;
    const float4* rs4 = (const float4*)g_rs;
    const float4* ga4 = (const float4*)gamma;
    const float4* be4 = (const float4*)beta;
    for (int c = threadIdx.x; c < D_IN / 4; c += 256) {
        const float4 v = hrow[c];
        const float4 m = mu4[c], rs = rs4[c], g = ga4[c], b = be4[c];
        float4 y;
        y.x = (v.x - m.x) * rs.x * g.x + b.x;
        y.y = (v.y - m.y) * rs.y * g.y + b.y;
        y.z = (v.z - m.z) * rs.z * g.z + b.z;
        y.w = (v.w - m.w) * rs.w * g.w + b.w;
        y.x = (y.x > 0.0f) ? y.x : expm1f(y.x);
        y.y = (y.y > 0.0f) ? y.y : expm1f(y.y);
        y.z = (y.z > 0.0f) ? y.z : expm1f(y.z);
        y.w = (y.w > 0.0f) ? y.w : expm1f(y.w);
        orow[c] = y;
    }
}

// ------------------------------- launch ----------------------------------------
extern "C" void kernel_launch(void* const* d_in, const int* in_sizes, int n_in,
                              void* d_out, int out_size) {
    const float* x     = (const float*)d_in[0];   // [10000,128]
    const float* xn    = (const float*)d_in[1];   // [60000,128]
    const float* sp    = (const float*)d_in[2];   // [10000,2]
    const float* W     = (const float*)d_in[3];   // [128,3000]
    const float* bias  = (const float*)d_in[4];   // [3000]
    const float* gamma = (const float*)d_in[5];   // [3000]
    const float* beta  = (const float*)d_in[6];   // [3000]

    float* out = (float*)d_out;
    float* z_out  = out;                                   // [10000,128]
    float* de_out = out + (size_t)N_SPOTS * D_LAT;         // [10000,3000]
    float* hr_out = de_out + (size_t)N_SPOTS * D_IN;       // [10000,768]

    int* idx_ptr;   cudaGetSymbolAddress((void**)&idx_ptr, g_idx);
    void *cnt_p, *cur_p, *sum_p, *ssq_p;
    cudaGetSymbolAddress(&cnt_p, g_cnt);
    cudaGetSymbolAddress(&cur_p, g_cur);
    cudaGetSymbolAddress(&sum_p, g_sum);
    cudaGetSymbolAddress(&ssq_p, g_sumsq);

    cudaMemsetAsync(cnt_p, 0, NCELLS * sizeof(int));
    cudaMemsetAsync(cur_p, 0, NCELLS * sizeof(int));
    cudaMemsetAsync(sum_p, 0, D_IN * sizeof(float));
    cudaMemsetAsync(ssq_p, 0, D_IN * sizeof(float));

    knn_count  <<<(N_SPOTS + 255) / 256, 256>>>((const float2*)sp);
    knn_scan   <<<1, 32>>>();
    knn_scatter<<<(N_SPOTS + 255) / 256, 256>>>((const float2*)sp);
    knn_search <<<(N_SPOTS + 127) / 128, 128>>>(idx_ptr);
    agg_kernel <<<N_SPOTS, 128>>>(x, xn, z_out, hr_out);
    gemm_kernel<<<dim3((D_IN + GN - 1) / GN, (N_SPOTS + GM - 1) / GM), 256>>>(z_out, W, bias);
    stats2_kernel<<<(D_IN + 127) / 128, 128>>>();
    bnelu_kernel<<<N_SPOTS, 256>>>(gamma, beta, de_out);
}

// round 4
// speedup vs baseline: 3.1690x; 1.1735x over previous
#include <cuda_runtime.h>
#include <cuda_bf16.h>
#include <math.h>
#include <stdint.h>

// Problem constants (fixed shapes)
#define N_SPOTS 10000
#define D_LAT   128
#define D_IN    3000
#define KNN_K   10
#define SCALE   6
#define BN_EPS  1e-4f

// KNN grid
#define GRID_D  40
#define CSZ     2.5f
#define INV_CSZ 0.4f
#define NCELLS  (GRID_D * GRID_D)
#define SLACK   0.5f

#define INF_F __int_as_float(0x7f800000)

// ---------------- scratch (device globals; no allocation allowed) -------------
__device__ int    g_idx[N_SPOTS * KNN_K];
__device__ __align__(16) float g_h[(size_t)N_SPOTS * D_IN];   // 120 MB GEMM output
__device__ int    g_cnt[NCELLS];
__device__ int    g_cur[NCELLS];
__device__ int    g_startc[NCELLS];
__device__ __align__(16) float2 g_sx[N_SPOTS];
__device__ int    g_si[N_SPOTS];
__device__ __align__(16) float g_sum[D_IN];
__device__ __align__(16) float g_sumsq[D_IN];
__device__ __align__(16) float g_mu[D_IN];
__device__ __align__(16) float g_rs[D_IN];

// lexicographic (d2, idx) compare: matches jax.lax.top_k stable tie-break
__device__ __forceinline__ bool lexless(float d1, int j1, float d2, int j2) {
    return (d1 < d2) || (d1 == d2 && j1 < j2);
}

__device__ __forceinline__ int cell_x(float x) {
    int c = (int)(x * INV_CSZ);
    return min(GRID_D - 1, max(0, c));
}

// ----------------------------- KNN: build grid ---------------------------------
__global__ void knn_count(const float2* __restrict__ sp) {
    const int i = blockIdx.x * 256 + threadIdx.x;
    if (i >= N_SPOTS) return;
    const float2 s = sp[i];
    atomicAdd(&g_cnt[cell_x(s.y) * GRID_D + cell_x(s.x)], 1);
}

// single-warp exclusive scan over 1600 cells
__global__ void knn_scan() {
    const int lane = threadIdx.x;           // 32 threads
    const int CH = NCELLS / 32;             // 50
    const int base = lane * CH;
    int s = 0;
    for (int k = 0; k < CH; k++) s += g_cnt[base + k];
    int inc = s;
#pragma unroll
    for (int o = 1; o < 32; o <<= 1) {
        int v = __shfl_up_sync(0xffffffffu, inc, o);
        if (lane >= o) inc += v;
    }
    int run = inc - s;                      // exclusive prefix of this chunk
    for (int k = 0; k < CH; k++) {
        const int c = g_cnt[base + k];
        g_startc[base + k] = run;
        run += c;
    }
}

__global__ void knn_scatter(const float2* __restrict__ sp) {
    const int i = blockIdx.x * 256 + threadIdx.x;
    if (i >= N_SPOTS) return;
    const float2 s = sp[i];
    const int c = cell_x(s.y) * GRID_D + cell_x(s.x);
    const int dst = g_startc[c] + atomicAdd(&g_cur[c], 1);
    g_sx[dst] = s;
    g_si[dst] = i;
}

// ----------------------------- KNN: ring search --------------------------------
// d2 must be BIT-EXACT vs reference (XLA lowers the K=2 dot without fma):
//   sq = rn(rn(x*x) + rn(y*y));  dot = rn(rn(xi*xj) + rn(yi*yj))
//   d2 = rn(rn(sqi + sqj) - 2*dot)
__device__ __forceinline__ void proc_cell(int c, int i, float mx, float my, float sqi,
                                          float* dd, int* jj,
                                          float& wd, int& wj, int& ws) {
    const int t0 = g_startc[c];
    const int t1 = t0 + g_cnt[c];
    for (int t = t0; t < t1; t++) {
        const int j = g_si[t];
        const float2 s = g_sx[t];
        if (j == i) continue;
        const float sqj = __fadd_rn(__fmul_rn(s.x, s.x), __fmul_rn(s.y, s.y));
        const float dot = __fadd_rn(__fmul_rn(mx, s.x), __fmul_rn(my, s.y));
        const float d2  = __fadd_rn(__fadd_rn(sqi, sqj), __fmul_rn(-2.0f, dot));
        if (lexless(d2, j, wd, wj)) {
#pragma unroll
            for (int k = 0; k < KNN_K; k++) if (k == ws) { dd[k] = d2; jj[k] = j; }
            wd = dd[0]; wj = jj[0]; ws = 0;
#pragma unroll
            for (int k = 1; k < KNN_K; k++)
                if (lexless(wd, wj, dd[k], jj[k])) { wd = dd[k]; wj = jj[k]; ws = k; }
        }
    }
}

__global__ void knn_search(int* __restrict__ idx_out) {
    const int p = blockIdx.x * 128 + threadIdx.x;   // sorted position (cell-local warps)
    if (p >= N_SPOTS) return;
    const float2 me = g_sx[p];
    const int i = g_si[p];
    const float sqi = __fadd_rn(__fmul_rn(me.x, me.x), __fmul_rn(me.y, me.y));
    const int cx = cell_x(me.x), cy = cell_x(me.y);

    float dd[KNN_K]; int jj[KNN_K];
#pragma unroll
    for (int k = 0; k < KNN_K; k++) { dd[k] = INF_F; jj[k] = 0x7fffffff; }
    float wd = INF_F; int wj = 0x7fffffff; int ws = 0;

    for (int R = 0; R <= GRID_D; R++) {
        if (R >= 2) {
            // unprocessed cells have Chebyshev >= R -> true d >= (R-1)*CSZ.
            // computed d2 >= true d2 - eps(~0.02) ; SLACK=0.5 covers eps.
            const float b = (float)(R - 1) * CSZ;
            if (wd + SLACK < b * b) break;   // wd==INF while <10 found -> no break
        }
        const int x0 = max(0, cx - R), x1 = min(GRID_D - 1, cx + R);
        const int y0 = max(0, cy - R), y1 = min(GRID_D - 1, cy + R);
        for (int yy = y0; yy <= y1; yy++) {
            if (yy == cy - R || yy == cy + R) {
                for (int xx = x0; xx <= x1; xx++)
                    proc_cell(yy * GRID_D + xx, i, me.x, me.y, sqi, dd, jj, wd, wj, ws);
            } else {
                if (cx - R >= 0)     proc_cell(yy * GRID_D + cx - R, i, me.x, me.y, sqi, dd, jj, wd, wj, ws);
                if (cx + R < GRID_D) proc_cell(yy * GRID_D + cx + R, i, me.x, me.y, sqi, dd, jj, wd, wj, ws);
            }
        }
    }
#pragma unroll
    for (int k = 0; k < KNN_K; k++) idx_out[i * KNN_K + k] = jj[k];
}

// --------------------------- aggregation --------------------------------------
__global__ void agg_kernel(const float* __restrict__ x,
                           const float* __restrict__ xn,
                           float* __restrict__ z_out,
                           float* __restrict__ hr_out) {
    const int i   = blockIdx.x;
    const int tid = threadIdx.x;          // 0..127
    const int lane = tid & 31, wrp = tid >> 5;

    __shared__ int   nb[KNN_K];
    __shared__ float red[4][KNN_K];
    __shared__ float neg_mean[KNN_K];

    if (tid < KNN_K) nb[tid] = g_idx[i * KNN_K + tid];
    __syncthreads();

    const float xi = x[(size_t)i * D_LAT + tid];
    float xv[KNN_K];
    float fd[KNN_K];
#pragma unroll
    for (int k = 0; k < KNN_K; k++) {
        const float v = x[(size_t)nb[k] * D_LAT + tid];
        xv[k] = v;
        const float d = v - xi;
        fd[k] = d * d;
    }
#pragma unroll
    for (int k = 0; k < KNN_K; k++) {
        float v = fd[k];
#pragma unroll
        for (int o = 16; o > 0; o >>= 1) v += __shfl_xor_sync(0xffffffffu, v, o);
        if (lane == 0) red[wrp][k] = v;
    }
    __syncthreads();
    if (tid < KNN_K) {
        const float s = red[0][tid] + red[1][tid] + red[2][tid] + red[3][tid];
        neg_mean[tid] = -(s * (1.0f / 128.0f));
    }
    __syncthreads();

    float m = neg_mean[0];
#pragma unroll
    for (int k = 1; k < KNN_K; k++) m = fmaxf(m, neg_mean[k]);
    float e[KNN_K], se = 0.0f;
#pragma unroll
    for (int k = 0; k < KNN_K; k++) { e[k] = expf(neg_mean[k] - m); se += e[k]; }
    float w[KNN_K];
#pragma unroll
    for (int k = 0; k < KNN_K; k++) w[k] = e[k] / se;

    float acc = 0.0f;
#pragma unroll
    for (int k = 0; k < KNN_K; k++) acc = __fmaf_rn(w[k], xv[k], acc);
    z_out[(size_t)i * D_LAT + tid] = acc;

#pragma unroll
    for (int s = 0; s < SCALE; s++) {
        float a = 0.0f;
#pragma unroll
        for (int k = 0; k < KNN_K; k++)
            a = __fmaf_rn(w[k], xn[((size_t)s * N_SPOTS + nb[k]) * D_LAT + tid], a);
        hr_out[(size_t)i * (SCALE * D_LAT) + s * D_LAT + tid] = a;
    }
}

// ------------------------------ GEMM (3xTF32 tensor cores) ---------------------
// h = z_lr @ W + b  [10000 x 3000], K=128.
// Each fp32 value v = hi + lo (tf32-rounded); acc += hi*hi + hi*lo + lo*hi.
// Block tile 128x128, k-slab 8, double buffered. Warp tile 32x64.
// Fused: bias add, store h, per-column sum/sumsq atomics (BN stats).

__device__ __forceinline__ float tf32_rna(float x) {
    uint32_t r;
    asm("cvt.rna.tf32.f32 %0, %1;" : "=r"(r) : "f"(x));
    return __uint_as_float(r);
}

__device__ __forceinline__ void split_tf32(float v, float& hi, float& lo) {
    hi = tf32_rna(v);
    lo = tf32_rna(v - hi);
}

__device__ __forceinline__ void mma_tf32(float* d, const uint32_t* a, const uint32_t* b) {
    asm volatile(
        "mma.sync.aligned.m16n8k8.row.col.f32.tf32.tf32.f32 "
        "{%0,%1,%2,%3}, {%4,%5,%6,%7}, {%8,%9}, {%0,%1,%2,%3};"
        : "+f"(d[0]), "+f"(d[1]), "+f"(d[2]), "+f"(d[3])
        : "r"(a[0]), "r"(a[1]), "r"(a[2]), "r"(a[3]), "r"(b[0]), "r"(b[1]));
}

#define GM 128
#define GN 128
#define GK 8
#define ASTRIDE 12      // float2 units per A row (8 used + 4 pad) -> conflict-free frags
#define BSTRIDE 132     // float2 units per B k-row (128 used + 4 pad)

__global__ void __launch_bounds__(256) gemm_kernel(const float* __restrict__ A,
                                                   const float* __restrict__ B,
                                                   const float* __restrict__ bias) {
    __shared__ float2 As2[2][GM][ASTRIDE];   // [buf][m][k] (hi,lo)
    __shared__ float2 Bs2[2][GK][BSTRIDE];   // [buf][k][n] (hi,lo)

    const int bm  = blockIdx.y * GM;
    const int bn  = blockIdx.x * GN;
    const int tid = threadIdx.x;
    const int lane = tid & 31;
    const int wrp  = tid >> 5;
    const int tg   = lane & 3;     // threadID in group (quad)
    const int gp   = lane >> 2;    // groupID
    const int m0w  = (wrp & 3) * 32;   // warp row offset in tile
    const int n0w  = (wrp >> 2) * 64;  // warp col offset in tile

    // --- global load indices ---
    const int arow_l = tid & 127;       // A row within tile
    const int ahalf  = tid >> 7;        // which 4-float chunk of the 8-float slab
    const int arow   = min(bm + arow_l, N_SPOTS - 1);
    const int bkr    = tid >> 5;        // B k-row within slab (0..7)
    const int bn4    = (tid & 31) * 4;  // B col within tile
    const int bcol   = min(bn + bn4, D_IN - 4);

    float4 ra, rb;
    ra = *(const float4*)(A + (size_t)arow * D_LAT + 0 + ahalf * 4);
    rb = *(const float4*)(B + (size_t)(0 + bkr) * D_IN + bcol);

    float acc[2][8][4];
#pragma unroll
    for (int mt = 0; mt < 2; mt++)
#pragma unroll
        for (int nt = 0; nt < 8; nt++)
#pragma unroll
            for (int q = 0; q < 4; q++) acc[mt][nt][q] = 0.0f;

#define CONV_STS(buf)                                                         \
    {                                                                         \
        float h0, l0, h1, l1, h2, l2, h3, l3;                                 \
        split_tf32(ra.x, h0, l0); split_tf32(ra.y, h1, l1);                   \
        split_tf32(ra.z, h2, l2); split_tf32(ra.w, h3, l3);                   \
        *(float4*)&As2[buf][arow_l][ahalf * 4 + 0] = make_float4(h0, l0, h1, l1); \
        *(float4*)&As2[buf][arow_l][ahalf * 4 + 2] = make_float4(h2, l2, h3, l3); \
        split_tf32(rb.x, h0, l0); split_tf32(rb.y, h1, l1);                   \
        split_tf32(rb.z, h2, l2); split_tf32(rb.w, h3, l3);                   \
        *(float4*)&Bs2[buf][bkr][bn4 + 0] = make_float4(h0, l0, h1, l1);      \
        *(float4*)&Bs2[buf][bkr][bn4 + 2] = make_float4(h2, l2, h3, l3);      \
    }

    CONV_STS(0);
    __syncthreads();

#pragma unroll 1
    for (int s = 0; s < D_LAT / GK; s++) {
        if (s < D_LAT / GK - 1) {
            const int k0 = (s + 1) * GK;
            ra = *(const float4*)(A + (size_t)arow * D_LAT + k0 + ahalf * 4);
            rb = *(const float4*)(B + (size_t)(k0 + bkr) * D_IN + bcol);
        }
        const int cur = s & 1;

        // A fragments for both mtiles (hi & lo)
        uint32_t ah[2][4], al[2][4];
#pragma unroll
        for (int mt = 0; mt < 2; mt++) {
            const int mr = m0w + mt * 16;
            float2 f0 = As2[cur][mr + gp][tg];
            float2 f1 = As2[cur][mr + gp + 8][tg];
            float2 f2 = As2[cur][mr + gp][tg + 4];
            float2 f3 = As2[cur][mr + gp + 8][tg + 4];
            ah[mt][0] = __float_as_uint(f0.x); al[mt][0] = __float_as_uint(f0.y);
            ah[mt][1] = __float_as_uint(f1.x); al[mt][1] = __float_as_uint(f1.y);
            ah[mt][2] = __float_as_uint(f2.x); al[mt][2] = __float_as_uint(f2.y);
            ah[mt][3] = __float_as_uint(f3.x); al[mt][3] = __float_as_uint(f3.y);
        }

#pragma unroll
        for (int nt = 0; nt < 8; nt++) {
            const int nc = n0w + nt * 8 + gp;
            float2 g0 = Bs2[cur][tg][nc];
            float2 g1 = Bs2[cur][tg + 4][nc];
            uint32_t bh[2] = { __float_as_uint(g0.x), __float_as_uint(g1.x) };
            uint32_t bl[2] = { __float_as_uint(g0.y), __float_as_uint(g1.y) };
#pragma unroll
            for (int mt = 0; mt < 2; mt++) {
                mma_tf32(acc[mt][nt], ah[mt], bh);   // hi*hi
                mma_tf32(acc[mt][nt], ah[mt], bl);   // hi*lo
                mma_tf32(acc[mt][nt], al[mt], bh);   // lo*hi
            }
        }

        if (s < D_LAT / GK - 1) {
            CONV_STS((s + 1) & 1);
            __syncthreads();
        }
    }

    // ---- epilogue: bias, store h, column sums ----
#pragma unroll
    for (int nt = 0; nt < 8; nt++) {
        const int col = bn + n0w + nt * 8 + tg * 2;
        if (col >= D_IN) continue;                 // col even, D_IN even -> pair safe
        const float bia0 = __ldg(&bias[col]);
        const float bia1 = __ldg(&bias[col + 1]);
        float s0 = 0.0f, ss0 = 0.0f, s1 = 0.0f, ss1 = 0.0f;
#pragma unroll
        for (int mt = 0; mt < 2; mt++) {
#pragma unroll
            for (int hf = 0; hf < 2; hf++) {
                const int row = bm + m0w + mt * 16 + gp + hf * 8;
                if (row < N_SPOTS) {
                    const float h0 = acc[mt][nt][hf * 2 + 0] + bia0;
                    const float h1 = acc[mt][nt][hf * 2 + 1] + bia1;
                    *(float2*)&g_h[(size_t)row * D_IN + col] = make_float2(h0, h1);
                    s0 += h0; ss0 = __fmaf_rn(h0, h0, ss0);
                    s1 += h1; ss1 = __fmaf_rn(h1, h1, ss1);
                }
            }
        }
        atomicAdd(&g_sum[col],     s0);
        atomicAdd(&g_sumsq[col],   ss0);
        atomicAdd(&g_sum[col + 1], s1);
        atomicAdd(&g_sumsq[col + 1], ss1);
    }
}

// -------------------------- finalize BN statistics ------------------------------
__global__ void stats2_kernel() {
    const int c = blockIdx.x * 128 + threadIdx.x;
    if (c >= D_IN) return;
    const float mu  = g_sum[c]   * (1.0f / (float)N_SPOTS);
    const float var = g_sumsq[c] * (1.0f / (float)N_SPOTS) - mu * mu;
    g_mu[c] = mu;
    g_rs[c] = 1.0f / sqrtf(var + BN_EPS);
}

// ----------------------------- BN + ELU ----------------------------------------
__global__ void bnelu_kernel(const float* __restrict__ gamma,
                             const float* __restrict__ beta,
                             float* __restrict__ out) {
    const int r = blockIdx.x;
    const float4* hrow = (const float4*)(g_h + (size_t)r * D_IN);
    float4* orow = (float4*)(out + (size_t)r * D_IN);
    const float4* mu4 = (const float4*)g_mu;
    const float4* rs4 = (const float4*)g_rs;
    const float4* ga4 = (const float4*)gamma;
    const float4* be4 = (const float4*)beta;
    for (int c = threadIdx.x; c < D_IN / 4; c += 256) {
        const float4 v = hrow[c];
        const float4 m = mu4[c], rs = rs4[c], g = ga4[c], b = be4[c];
        float4 y;
        y.x = (v.x - m.x) * rs.x * g.x + b.x;
        y.y = (v.y - m.y) * rs.y * g.y + b.y;
        y.z = (v.z - m.z) * rs.z * g.z + b.z;
        y.w = (v.w - m.w) * rs.w * g.w + b.w;
        y.x = (y.x > 0.0f) ? y.x : expm1f(y.x);
        y.y = (y.y > 0.0f) ? y.y : expm1f(y.y);
        y.z = (y.z > 0.0f) ? y.z : expm1f(y.z);
        y.w = (y.w > 0.0f) ? y.w : expm1f(y.w);
        orow[c] = y;
    }
}

// ------------------------------- launch ----------------------------------------
extern "C" void kernel_launch(void* const* d_in, const int* in_sizes, int n_in,
                              void* d_out, int out_size) {
    const float* x     = (const float*)d_in[0];   // [10000,128]
    const float* xn    = (const float*)d_in[1];   // [60000,128]
    const float* sp    = (const float*)d_in[2];   // [10000,2]
    const float* W     = (const float*)d_in[3];   // [128,3000]
    const float* bias  = (const float*)d_in[4];   // [3000]
    const float* gamma = (const float*)d_in[5];   // [3000]
    const float* beta  = (const float*)d_in[6];   // [3000]

    float* out = (float*)d_out;
    float* z_out  = out;                                   // [10000,128]
    float* de_out = out + (size_t)N_SPOTS * D_LAT;         // [10000,3000]
    float* hr_out = de_out + (size_t)N_SPOTS * D_IN;       // [10000,768]

    int* idx_ptr;   cudaGetSymbolAddress((void**)&idx_ptr, g_idx);
    void *cnt_p, *cur_p, *sum_p, *ssq_p;
    cudaGetSymbolAddress(&cnt_p, g_cnt);
    cudaGetSymbolAddress(&cur_p, g_cur);
    cudaGetSymbolAddress(&sum_p, g_sum);
    cudaGetSymbolAddress(&ssq_p, g_sumsq);

    cudaMemsetAsync(cnt_p, 0, NCELLS * sizeof(int));
    cudaMemsetAsync(cur_p, 0, NCELLS * sizeof(int));
    cudaMemsetAsync(sum_p, 0, D_IN * sizeof(float));
    cudaMemsetAsync(ssq_p, 0, D_IN * sizeof(float));

    knn_count  <<<(N_SPOTS + 255) / 256, 256>>>((const float2*)sp);
    knn_scan   <<<1, 32>>>();
    knn_scatter<<<(N_SPOTS + 255) / 256, 256>>>((const float2*)sp);
    knn_search <<<(N_SPOTS + 127) / 128, 128>>>(idx_ptr);
    agg_kernel <<<N_SPOTS, 128>>>(x, xn, z_out, hr_out);
    gemm_kernel<<<dim3((D_IN + GN - 1) / GN, (N_SPOTS + GM - 1) / GM), 256>>>(z_out, W, bias);
    stats2_kernel<<<(D_IN + 127) / 128, 128>>>();
    bnelu_kernel<<<N_SPOTS, 256>>>(gamma, beta, de_out);
}

// round 5
// speedup vs baseline: 3.3635x; 1.0614x over previous
#include <cuda_runtime.h>
#include <cuda_bf16.h>
#include <math.h>
#include <stdint.h>

// Problem constants (fixed shapes)
#define N_SPOTS 10000
#define D_LAT   128
#define D_IN    3000
#define KNN_K   10
#define SCALE   6
#define BN_EPS  1e-4f

// KNN grid
#define GRID_D  40
#define CSZ     2.5f
#define INV_CSZ 0.4f
#define NCELLS  (GRID_D * GRID_D)
#define SLACK   0.5f

#define INF_F __int_as_float(0x7f800000)

// ---------------- scratch (device globals; no allocation allowed) -------------
__device__ int    g_idx[N_SPOTS * KNN_K];
__device__ int    g_cnt[NCELLS];
__device__ int    g_cur[NCELLS];
__device__ int    g_startc[NCELLS];
__device__ __align__(16) float2 g_sx[N_SPOTS];
__device__ int    g_si[N_SPOTS];
__device__ __align__(16) float g_G[D_LAT * D_LAT];   // Z^T Z
__device__ __align__(16) float g_s[D_LAT];           // col-sum of Z
__device__ __align__(16) float g_mu[D_IN];
__device__ __align__(16) float g_rs[D_IN];

// lexicographic (d2, idx) compare: matches jax.lax.top_k stable tie-break
__device__ __forceinline__ bool lexless(float d1, int j1, float d2, int j2) {
    return (d1 < d2) || (d1 == d2 && j1 < j2);
}

__device__ __forceinline__ int cell_x(float x) {
    int c = (int)(x * INV_CSZ);
    return min(GRID_D - 1, max(0, c));
}

// ----------------------------- KNN: build grid ---------------------------------
__global__ void knn_count(const float2* __restrict__ sp) {
    const int i = blockIdx.x * 256 + threadIdx.x;
    if (i >= N_SPOTS) return;
    const float2 s = sp[i];
    atomicAdd(&g_cnt[cell_x(s.y) * GRID_D + cell_x(s.x)], 1);
}

// single-warp exclusive scan over 1600 cells
__global__ void knn_scan() {
    const int lane = threadIdx.x;           // 32 threads
    const int CH = NCELLS / 32;             // 50
    const int base = lane * CH;
    int s = 0;
    for (int k = 0; k < CH; k++) s += g_cnt[base + k];
    int inc = s;
#pragma unroll
    for (int o = 1; o < 32; o <<= 1) {
        int v = __shfl_up_sync(0xffffffffu, inc, o);
        if (lane >= o) inc += v;
    }
    int run = inc - s;                      // exclusive prefix of this chunk
    for (int k = 0; k < CH; k++) {
        const int c = g_cnt[base + k];
        g_startc[base + k] = run;
        run += c;
    }
}

__global__ void knn_scatter(const float2* __restrict__ sp) {
    const int i = blockIdx.x * 256 + threadIdx.x;
    if (i >= N_SPOTS) return;
    const float2 s = sp[i];
    const int c = cell_x(s.y) * GRID_D + cell_x(s.x);
    const int dst = g_startc[c] + atomicAdd(&g_cur[c], 1);
    g_sx[dst] = s;
    g_si[dst] = i;
}

// ----------------------------- KNN: ring search --------------------------------
// d2 must be BIT-EXACT vs reference (XLA lowers the K=2 dot without fma):
//   sq = rn(rn(x*x) + rn(y*y));  dot = rn(rn(xi*xj) + rn(yi*yj))
//   d2 = rn(rn(sqi + sqj) - 2*dot)
__device__ __forceinline__ void proc_cell(int c, int i, float mx, float my, float sqi,
                                          float* dd, int* jj,
                                          float& wd, int& wj, int& ws) {
    const int t0 = g_startc[c];
    const int t1 = t0 + g_cnt[c];
    for (int t = t0; t < t1; t++) {
        const int j = g_si[t];
        const float2 s = g_sx[t];
        if (j == i) continue;
        const float sqj = __fadd_rn(__fmul_rn(s.x, s.x), __fmul_rn(s.y, s.y));
        const float dot = __fadd_rn(__fmul_rn(mx, s.x), __fmul_rn(my, s.y));
        const float d2  = __fadd_rn(__fadd_rn(sqi, sqj), __fmul_rn(-2.0f, dot));
        if (lexless(d2, j, wd, wj)) {
#pragma unroll
            for (int k = 0; k < KNN_K; k++) if (k == ws) { dd[k] = d2; jj[k] = j; }
            wd = dd[0]; wj = jj[0]; ws = 0;
#pragma unroll
            for (int k = 1; k < KNN_K; k++)
                if (lexless(wd, wj, dd[k], jj[k])) { wd = dd[k]; wj = jj[k]; ws = k; }
        }
    }
}

__global__ void knn_search(int* __restrict__ idx_out) {
    const int p = blockIdx.x * 128 + threadIdx.x;   // sorted position (cell-local warps)
    if (p >= N_SPOTS) return;
    const float2 me = g_sx[p];
    const int i = g_si[p];
    const float sqi = __fadd_rn(__fmul_rn(me.x, me.x), __fmul_rn(me.y, me.y));
    const int cx = cell_x(me.x), cy = cell_x(me.y);

    float dd[KNN_K]; int jj[KNN_K];
#pragma unroll
    for (int k = 0; k < KNN_K; k++) { dd[k] = INF_F; jj[k] = 0x7fffffff; }
    float wd = INF_F; int wj = 0x7fffffff; int ws = 0;

    for (int R = 0; R <= GRID_D; R++) {
        if (R >= 2) {
            const float b = (float)(R - 1) * CSZ;
            if (wd + SLACK < b * b) break;
        }
        const int x0 = max(0, cx - R), x1 = min(GRID_D - 1, cx + R);
        const int y0 = max(0, cy - R), y1 = min(GRID_D - 1, cy + R);
        for (int yy = y0; yy <= y1; yy++) {
            if (yy == cy - R || yy == cy + R) {
                for (int xx = x0; xx <= x1; xx++)
                    proc_cell(yy * GRID_D + xx, i, me.x, me.y, sqi, dd, jj, wd, wj, ws);
            } else {
                if (cx - R >= 0)     proc_cell(yy * GRID_D + cx - R, i, me.x, me.y, sqi, dd, jj, wd, wj, ws);
                if (cx + R < GRID_D) proc_cell(yy * GRID_D + cx + R, i, me.x, me.y, sqi, dd, jj, wd, wj, ws);
            }
        }
    }
#pragma unroll
    for (int k = 0; k < KNN_K; k++) idx_out[i * KNN_K + k] = jj[k];
}

// --------------------------- aggregation --------------------------------------
__global__ void agg_kernel(const float* __restrict__ x,
                           const float* __restrict__ xn,
                           float* __restrict__ z_out,
                           float* __restrict__ hr_out) {
    const int i   = blockIdx.x;
    const int tid = threadIdx.x;          // 0..127
    const int lane = tid & 31, wrp = tid >> 5;

    __shared__ int   nb[KNN_K];
    __shared__ float red[4][KNN_K];
    __shared__ float neg_mean[KNN_K];

    if (tid < KNN_K) nb[tid] = g_idx[i * KNN_K + tid];
    __syncthreads();

    const float xi = x[(size_t)i * D_LAT + tid];
    float xv[KNN_K];
    float fd[KNN_K];
#pragma unroll
    for (int k = 0; k < KNN_K; k++) {
        const float v = x[(size_t)nb[k] * D_LAT + tid];
        xv[k] = v;
        const float d = v - xi;
        fd[k] = d * d;
    }
#pragma unroll
    for (int k = 0; k < KNN_K; k++) {
        float v = fd[k];
#pragma unroll
        for (int o = 16; o > 0; o >>= 1) v += __shfl_xor_sync(0xffffffffu, v, o);
        if (lane == 0) red[wrp][k] = v;
    }
    __syncthreads();
    if (tid < KNN_K) {
        const float s = red[0][tid] + red[1][tid] + red[2][tid] + red[3][tid];
        neg_mean[tid] = -(s * (1.0f / 128.0f));
    }
    __syncthreads();

    float m = neg_mean[0];
#pragma unroll
    for (int k = 1; k < KNN_K; k++) m = fmaxf(m, neg_mean[k]);
    float e[KNN_K], se = 0.0f;
#pragma unroll
    for (int k = 0; k < KNN_K; k++) { e[k] = expf(neg_mean[k] - m); se += e[k]; }
    float w[KNN_K];
#pragma unroll
    for (int k = 0; k < KNN_K; k++) w[k] = e[k] / se;

    float acc = 0.0f;
#pragma unroll
    for (int k = 0; k < KNN_K; k++) acc = __fmaf_rn(w[k], xv[k], acc);
    z_out[(size_t)i * D_LAT + tid] = acc;

#pragma unroll
    for (int s = 0; s < SCALE; s++) {
        float a = 0.0f;
#pragma unroll
        for (int k = 0; k < KNN_K; k++)
            a = __fmaf_rn(w[k], xn[((size_t)s * N_SPOTS + nb[k]) * D_LAT + tid], a);
        hr_out[(size_t)i * (SCALE * D_LAT) + s * D_LAT + tid] = a;
    }
}

// --------------------------- Gram: G = Z^T Z, s = colsum(Z) --------------------
#define GRAM_BLOCKS 80
__global__ void __launch_bounds__(256) gram_kernel(const float* __restrict__ z) {
    __shared__ float zrow[D_LAT];
    const int tid = threadIdx.x;
    const int i_own = tid >> 1;           // G row this thread owns
    const int jb    = (tid & 1) * 64;     // half of the columns

    float acc[64];
#pragma unroll
    for (int q = 0; q < 64; q++) acc[q] = 0.0f;
    float s_loc = 0.0f;

    for (int m = blockIdx.x; m < N_SPOTS; m += GRAM_BLOCKS) {
        if (tid < D_LAT) zrow[tid] = z[(size_t)m * D_LAT + tid];
        __syncthreads();
        const float zi = zrow[i_own];
#pragma unroll
        for (int q = 0; q < 64; q++) acc[q] = __fmaf_rn(zi, zrow[jb + q], acc[q]);
        if (tid < D_LAT) s_loc += zrow[tid];
        __syncthreads();
    }
#pragma unroll
    for (int q = 0; q < 64; q++) atomicAdd(&g_G[i_own * D_LAT + jb + q], acc[q]);
    if (tid < D_LAT) atomicAdd(&g_s[tid], s_loc);
}

// --------------------------- BN stats from Gram --------------------------------
// For column c: sum_m h = s.w_c + N*b_c ; sum_m h^2 = w_c^T G w_c + 2 b_c (s.w_c) + N b_c^2
__global__ void __launch_bounds__(256) stats_kernel(const float* __restrict__ W,
                                                    const float* __restrict__ bias) {
    __shared__ float Gs[D_LAT][65];   // half of G (padded)
    __shared__ float ws[8][D_LAT];
    __shared__ float ss[D_LAT];

    const int tid = threadIdx.x;
    const int wrp = tid >> 5, lane = tid & 31;
    const int c0 = blockIdx.x * 8;
    const int c  = c0 + wrp;

    for (int idx = tid; idx < 8 * D_LAT; idx += 256) {
        const int cc = idx & 7, i = idx >> 3;
        ws[cc][i] = W[(size_t)i * D_IN + c0 + cc];
    }
    if (tid < D_LAT) ss[tid] = g_s[tid];

    float tpart[4] = {0.0f, 0.0f, 0.0f, 0.0f};
    for (int half = 0; half < 2; half++) {
        __syncthreads();
        for (int idx = tid; idx < D_LAT * 64; idx += 256) {
            const int i = idx >> 6, jj = idx & 63;
            Gs[i][jj] = g_G[i * D_LAT + half * 64 + jj];
        }
        __syncthreads();
#pragma unroll
        for (int ii = 0; ii < 4; ii++) {
            const int i = lane + ii * 32;
            float t = tpart[ii];
            const float* wr = &ws[wrp][half * 64];
#pragma unroll
            for (int jj = 0; jj < 64; jj++) t = __fmaf_rn(Gs[i][jj], wr[jj], t);
            tpart[ii] = t;
        }
    }

    float u = 0.0f, sw = 0.0f;
#pragma unroll
    for (int ii = 0; ii < 4; ii++) {
        const int i = lane + ii * 32;
        const float wi = ws[wrp][i];
        u  = __fmaf_rn(wi, tpart[ii], u);
        sw = __fmaf_rn(ss[i], wi, sw);
    }
#pragma unroll
    for (int o = 16; o > 0; o >>= 1) {
        u  += __shfl_xor_sync(0xffffffffu, u, o);
        sw += __shfl_xor_sync(0xffffffffu, sw, o);
    }
    if (lane == 0) {
        const float b   = bias[c];
        const float mu  = sw * (1.0f / (float)N_SPOTS) + b;
        const float eh2 = (u + 2.0f * b * sw) * (1.0f / (float)N_SPOTS) + b * b;
        const float var = eh2 - mu * mu;
        g_mu[c] = mu;
        g_rs[c] = 1.0f / sqrtf(var + BN_EPS);
    }
}

// ------------------------------ GEMM (3x bf16 tensor cores) --------------------
// de_feat = ELU(BN(z @ W + b))  [10000 x 3000], K=128.
// v = hi + lo (bf16); acc += hi*hi + hi*lo + lo*hi (lo*lo ~2^-18 dropped).
// Block tile 128x128, k-slab 16, double buffered. Warp tile 32x64.
// Epilogue: bias + BN (mu/rs precomputed via Gram) + ELU, write de_out directly.

__device__ __forceinline__ void split_bf(float v, __nv_bfloat16& h, __nv_bfloat16& l) {
    h = __float2bfloat16_rn(v);
    l = __float2bfloat16_rn(v - __bfloat162float(h));
}

__device__ __forceinline__ uint32_t pack2(__nv_bfloat16 a, __nv_bfloat16 b) {
    __nv_bfloat162 t; t.x = a; t.y = b;     // .x = low 16 bits = first (lower-k) element
    return *reinterpret_cast<uint32_t*>(&t);
}

__device__ __forceinline__ void mma_bf16(float* d, const uint32_t* a, const uint32_t* b) {
    asm volatile(
        "mma.sync.aligned.m16n8k16.row.col.f32.bf16.bf16.f32 "
        "{%0,%1,%2,%3}, {%4,%5,%6,%7}, {%8,%9}, {%0,%1,%2,%3};"
        : "+f"(d[0]), "+f"(d[1]), "+f"(d[2]), "+f"(d[3])
        : "r"(a[0]), "r"(a[1]), "r"(a[2]), "r"(a[3]), "r"(b[0]), "r"(b[1]));
}

#define GM 128
#define GN 128
#define GK 16
#define ASTR 20    // uint32 per A row: words 0..7 hi (kpairs), 8..15 lo, 4 pad
#define BSTR 136   // uint32 per B kpair row: 128 n + 8 pad

__global__ void __launch_bounds__(256) gemm_kernel(const float* __restrict__ A,
                                                   const float* __restrict__ B,
                                                   const float* __restrict__ bias,
                                                   const float* __restrict__ gamma,
                                                   const float* __restrict__ beta,
                                                   float* __restrict__ de_out) {
    __shared__ __align__(16) uint32_t As[2][GM][ASTR];   // [buf][m][kpair(hi:0-7, lo:8-15)]
    __shared__ __align__(16) uint32_t Bs[2][16][BSTR];   // [buf][kpair(hi:0-7, lo:8-15)][n]

    const int bm  = blockIdx.y * GM;
    const int bn  = blockIdx.x * GN;
    const int tid = threadIdx.x;
    const int lane = tid & 31;
    const int wrp  = tid >> 5;
    const int tg   = lane & 3;     // threadID in quad
    const int gp   = lane >> 2;    // groupID
    const int m0w  = (wrp & 3) * 32;   // warp row offset in tile
    const int n0w  = (wrp >> 2) * 64;  // warp col offset in tile

    // --- global load indices ---
    const int arow_l = tid & 127;       // A row within tile
    const int ahalf  = tid >> 7;        // k 0..7 or 8..15 of slab
    const int arow   = min(bm + arow_l, N_SPOTS - 1);
    const int bkp    = tid >> 5;        // B kpair within slab (0..7)
    const int bn4    = (tid & 31) * 4;  // B col within tile
    const int bcol   = min(bn + bn4, D_IN - 4);

    float4 ra0, ra1, rb0, rb1;
    ra0 = *(const float4*)(A + (size_t)arow * D_LAT + ahalf * 8);
    ra1 = *(const float4*)(A + (size_t)arow * D_LAT + ahalf * 8 + 4);
    rb0 = *(const float4*)(B + (size_t)(2 * bkp)     * D_IN + bcol);
    rb1 = *(const float4*)(B + (size_t)(2 * bkp + 1) * D_IN + bcol);

    float acc[2][8][4];
#pragma unroll
    for (int mt = 0; mt < 2; mt++)
#pragma unroll
        for (int nt = 0; nt < 8; nt++)
#pragma unroll
            for (int q = 0; q < 4; q++) acc[mt][nt][q] = 0.0f;

#define CONV_STS(buf)                                                          \
    {                                                                          \
        float va[8] = {ra0.x, ra0.y, ra0.z, ra0.w, ra1.x, ra1.y, ra1.z, ra1.w};\
        __nv_bfloat16 h[8], l[8];                                              \
        _Pragma("unroll")                                                      \
        for (int q = 0; q < 8; q++) split_bf(va[q], h[q], l[q]);               \
        uint4 hw, lw;                                                          \
        hw.x = pack2(h[0], h[1]); hw.y = pack2(h[2], h[3]);                    \
        hw.z = pack2(h[4], h[5]); hw.w = pack2(h[6], h[7]);                    \
        lw.x = pack2(l[0], l[1]); lw.y = pack2(l[2], l[3]);                    \
        lw.z = pack2(l[4], l[5]); lw.w = pack2(l[6], l[7]);                    \
        *(uint4*)&As[buf][arow_l][ahalf * 4]     = hw;                         \
        *(uint4*)&As[buf][arow_l][8 + ahalf * 4] = lw;                         \
        float v0[4] = {rb0.x, rb0.y, rb0.z, rb0.w};                            \
        float v1[4] = {rb1.x, rb1.y, rb1.z, rb1.w};                            \
        __nv_bfloat16 h0[4], l0[4], h1[4], l1[4];                              \
        _Pragma("unroll")                                                      \
        for (int q = 0; q < 4; q++) { split_bf(v0[q], h0[q], l0[q]);           \
                                      split_bf(v1[q], h1[q], l1[q]); }         \
        uint4 bhw, blw;                                                        \
        bhw.x = pack2(h0[0], h1[0]); bhw.y = pack2(h0[1], h1[1]);              \
        bhw.z = pack2(h0[2], h1[2]); bhw.w = pack2(h0[3], h1[3]);              \
        blw.x = pack2(l0[0], l1[0]); blw.y = pack2(l0[1], l1[1]);              \
        blw.z = pack2(l0[2], l1[2]); blw.w = pack2(l0[3], l1[3]);              \
        *(uint4*)&Bs[buf][bkp][bn4]     = bhw;                                 \
        *(uint4*)&Bs[buf][8 + bkp][bn4] = blw;                                 \
    }

    CONV_STS(0);
    __syncthreads();

#pragma unroll 1
    for (int s = 0; s < D_LAT / GK; s++) {
        if (s < D_LAT / GK - 1) {
            const int k0 = (s + 1) * GK;
            ra0 = *(const float4*)(A + (size_t)arow * D_LAT + k0 + ahalf * 8);
            ra1 = *(const float4*)(A + (size_t)arow * D_LAT + k0 + ahalf * 8 + 4);
            rb0 = *(const float4*)(B + (size_t)(k0 + 2 * bkp)     * D_IN + bcol);
            rb1 = *(const float4*)(B + (size_t)(k0 + 2 * bkp + 1) * D_IN + bcol);
        }
        const int cur = s & 1;

        uint32_t ah[2][4], al[2][4];
#pragma unroll
        for (int mt = 0; mt < 2; mt++) {
            const int mr = m0w + mt * 16;
            ah[mt][0] = As[cur][mr + gp][tg];
            ah[mt][1] = As[cur][mr + gp + 8][tg];
            ah[mt][2] = As[cur][mr + gp][tg + 4];
            ah[mt][3] = As[cur][mr + gp + 8][tg + 4];
            al[mt][0] = As[cur][mr + gp][8 + tg];
            al[mt][1] = As[cur][mr + gp + 8][8 + tg];
            al[mt][2] = As[cur][mr + gp][8 + tg + 4];
            al[mt][3] = As[cur][mr + gp + 8][8 + tg + 4];
        }

#pragma unroll
        for (int nt = 0; nt < 8; nt++) {
            const int nc = n0w + nt * 8 + gp;
            uint32_t bh[2] = { Bs[cur][tg][nc],     Bs[cur][tg + 4][nc] };
            uint32_t bl[2] = { Bs[cur][8 + tg][nc], Bs[cur][8 + tg + 4][nc] };
#pragma unroll
            for (int mt = 0; mt < 2; mt++) {
                mma_bf16(acc[mt][nt], ah[mt], bh);   // hi*hi
                mma_bf16(acc[mt][nt], ah[mt], bl);   // hi*lo
                mma_bf16(acc[mt][nt], al[mt], bh);   // lo*hi
            }
        }

        if (s < D_LAT / GK - 1) {
            CONV_STS((s + 1) & 1);
            __syncthreads();
        }
    }

    // ---- epilogue: bias + BN + ELU, write de_out directly ----
#pragma unroll
    for (int nt = 0; nt < 8; nt++) {
        const int col = bn + n0w + nt * 8 + tg * 2;
        if (col >= D_IN) continue;          // col even, D_IN even -> col+1 also valid
        const float bia0 = __ldg(&bias[col]),  bia1 = __ldg(&bias[col + 1]);
        const float mu0  = g_mu[col],          mu1  = g_mu[col + 1];
        const float rs0  = g_rs[col],          rs1  = g_rs[col + 1];
        const float ga0  = __ldg(&gamma[col]), ga1  = __ldg(&gamma[col + 1]);
        const float be0  = __ldg(&beta[col]),  be1  = __ldg(&beta[col + 1]);
#pragma unroll
        for (int mt = 0; mt < 2; mt++) {
#pragma unroll
            for (int hf = 0; hf < 2; hf++) {
                const int row = bm + m0w + mt * 16 + gp + hf * 8;
                if (row >= N_SPOTS) continue;
                const float h0 = acc[mt][nt][hf * 2 + 0] + bia0;
                const float h1 = acc[mt][nt][hf * 2 + 1] + bia1;
                float y0 = (h0 - mu0) * rs0 * ga0 + be0;
                float y1 = (h1 - mu1) * rs1 * ga1 + be1;
                y0 = (y0 > 0.0f) ? y0 : expm1f(y0);
                y1 = (y1 > 0.0f) ? y1 : expm1f(y1);
                *(float2*)&de_out[(size_t)row * D_IN + col] = make_float2(y0, y1);
            }
        }
    }
}

// ------------------------------- launch ----------------------------------------
extern "C" void kernel_launch(void* const* d_in, const int* in_sizes, int n_in,
                              void* d_out, int out_size) {
    const float* x     = (const float*)d_in[0];   // [10000,128]
    const float* xn    = (const float*)d_in[1];   // [60000,128]
    const float* sp    = (const float*)d_in[2];   // [10000,2]
    const float* W     = (const float*)d_in[3];   // [128,3000]
    const float* bias  = (const float*)d_in[4];   // [3000]
    const float* gamma = (const float*)d_in[5];   // [3000]
    const float* beta  = (const float*)d_in[6];   // [3000]

    float* out = (float*)d_out;
    float* z_out  = out;                                   // [10000,128]
    float* de_out = out + (size_t)N_SPOTS * D_LAT;         // [10000,3000]
    float* hr_out = de_out + (size_t)N_SPOTS * D_IN;       // [10000,768]

    int* idx_ptr;   cudaGetSymbolAddress((void**)&idx_ptr, g_idx);
    void *cnt_p, *cur_p, *G_p, *s_p;
    cudaGetSymbolAddress(&cnt_p, g_cnt);
    cudaGetSymbolAddress(&cur_p, g_cur);
    cudaGetSymbolAddress(&G_p,   g_G);
    cudaGetSymbolAddress(&s_p,   g_s);

    cudaMemsetAsync(cnt_p, 0, NCELLS * sizeof(int));
    cudaMemsetAsync(cur_p, 0, NCELLS * sizeof(int));
    cudaMemsetAsync(G_p,   0, D_LAT * D_LAT * sizeof(float));
    cudaMemsetAsync(s_p,   0, D_LAT * sizeof(float));

    knn_count  <<<(N_SPOTS + 255) / 256, 256>>>((const float2*)sp);
    knn_scan   <<<1, 32>>>();
    knn_scatter<<<(N_SPOTS + 255) / 256, 256>>>((const float2*)sp);
    knn_search <<<(N_SPOTS + 127) / 128, 128>>>(idx_ptr);
    agg_kernel <<<N_SPOTS, 128>>>(x, xn, z_out, hr_out);
    gram_kernel<<<GRAM_BLOCKS, 256>>>(z_out);
    stats_kernel<<<D_IN / 8, 256>>>(W, bias);
    gemm_kernel<<<dim3((D_IN + GN - 1) / GN, (N_SPOTS + GM - 1) / GM), 256>>>(
        z_out, W, bias, gamma, beta, de_out);
}

// round 6
// speedup vs baseline: 3.3638x; 1.0001x over previous
#include <cuda_runtime.h>
#include <cuda_bf16.h>
#include <math.h>
#include <stdint.h>

// Problem constants (fixed shapes)
#define N_SPOTS 10000
#define D_LAT   128
#define D_IN    3000
#define KNN_K   10
#define SCALE   6
#define BN_EPS  1e-4f

// KNN grid
#define GRID_D  40
#define CSZ     2.5f
#define INV_CSZ 0.4f
#define NCELLS  (GRID_D * GRID_D)
#define SLACK   0.5f

#define INF_F __int_as_float(0x7f800000)

// ---------------- scratch (device globals; no allocation allowed) -------------
__device__ int    g_idx[N_SPOTS * KNN_K];
__device__ int    g_cnt[NCELLS];
__device__ int    g_cur[NCELLS];
__device__ __align__(8)  int2   g_range[NCELLS];      // (start, count)
__device__ __align__(16) float4 g_sp4[N_SPOTS];       // (x, y, idx-bits, 0)
__device__ __align__(16) float g_G[D_LAT * D_LAT];    // Z^T Z
__device__ __align__(16) float g_s[D_LAT];            // col-sum of Z
__device__ __align__(16) float g_mu[D_IN];
__device__ __align__(16) float g_rs[D_IN];
// pre-split bf16 hi/lo operands (packed bf16x2 per k-pair)
__device__ __align__(16) uint32_t g_zh[(size_t)N_SPOTS * 64];
__device__ __align__(16) uint32_t g_zl[(size_t)N_SPOTS * 64];
__device__ __align__(16) uint32_t g_bh[(size_t)64 * D_IN];
__device__ __align__(16) uint32_t g_bl[(size_t)64 * D_IN];

// lexicographic (d2, idx) compare: matches jax.lax.top_k stable tie-break
__device__ __forceinline__ bool lexless(float d1, int j1, float d2, int j2) {
    return (d1 < d2) || (d1 == d2 && j1 < j2);
}

__device__ __forceinline__ int cell_x(float x) {
    int c = (int)(x * INV_CSZ);
    return min(GRID_D - 1, max(0, c));
}

__device__ __forceinline__ void split_bf(float v, __nv_bfloat16& h, __nv_bfloat16& l) {
    h = __float2bfloat16_rn(v);
    l = __float2bfloat16_rn(v - __bfloat162float(h));
}

__device__ __forceinline__ uint32_t pack2(__nv_bfloat16 a, __nv_bfloat16 b) {
    __nv_bfloat162 t; t.x = a; t.y = b;     // .x = low 16 bits = lower-k element
    return *reinterpret_cast<uint32_t*>(&t);
}

// ----------------------------- KNN: build grid ---------------------------------
__global__ void knn_count(const float2* __restrict__ sp) {
    const int i = blockIdx.x * 256 + threadIdx.x;
    if (i >= N_SPOTS) return;
    const float2 s = sp[i];
    atomicAdd(&g_cnt[cell_x(s.y) * GRID_D + cell_x(s.x)], 1);
}

// single-warp exclusive scan over 1600 cells
__global__ void knn_scan() {
    const int lane = threadIdx.x;           // 32 threads
    const int CH = NCELLS / 32;             // 50
    const int base = lane * CH;
    int s = 0;
    for (int k = 0; k < CH; k++) s += g_cnt[base + k];
    int inc = s;
#pragma unroll
    for (int o = 1; o < 32; o <<= 1) {
        int v = __shfl_up_sync(0xffffffffu, inc, o);
        if (lane >= o) inc += v;
    }
    int run = inc - s;                      // exclusive prefix of this chunk
    for (int k = 0; k < CH; k++) {
        const int c = g_cnt[base + k];
        g_range[base + k] = make_int2(run, c);
        run += c;
    }
}

__global__ void knn_scatter(const float2* __restrict__ sp) {
    const int i = blockIdx.x * 256 + threadIdx.x;
    if (i >= N_SPOTS) return;
    const float2 s = sp[i];
    const int c = cell_x(s.y) * GRID_D + cell_x(s.x);
    const int dst = g_range[c].x + atomicAdd(&g_cur[c], 1);
    g_sp4[dst] = make_float4(s.x, s.y, __int_as_float(i), 0.0f);
}

// ----------------------------- KNN: ring search --------------------------------
// d2 must be BIT-EXACT vs reference (XLA lowers the K=2 dot without fma):
//   sq = rn(rn(x*x) + rn(y*y));  dot = rn(rn(xi*xj) + rn(yi*yj))
//   d2 = rn(rn(sqi + sqj) - 2*dot)
__device__ __forceinline__ void proc_cell(int c, int i, float mx, float my, float sqi,
                                          float* dd, int* jj,
                                          float& wd, int& wj, int& ws) {
    const int2 rg = g_range[c];
    const int t1 = rg.x + rg.y;
    for (int t = rg.x; t < t1; t++) {
        const float4 s = g_sp4[t];
        const int j = __float_as_int(s.z);
        if (j == i) continue;
        const float sqj = __fadd_rn(__fmul_rn(s.x, s.x), __fmul_rn(s.y, s.y));
        const float dot = __fadd_rn(__fmul_rn(mx, s.x), __fmul_rn(my, s.y));
        const float d2  = __fadd_rn(__fadd_rn(sqi, sqj), __fmul_rn(-2.0f, dot));
        if (lexless(d2, j, wd, wj)) {
#pragma unroll
            for (int k = 0; k < KNN_K; k++) if (k == ws) { dd[k] = d2; jj[k] = j; }
            wd = dd[0]; wj = jj[0]; ws = 0;
#pragma unroll
            for (int k = 1; k < KNN_K; k++)
                if (lexless(wd, wj, dd[k], jj[k])) { wd = dd[k]; wj = jj[k]; ws = k; }
        }
    }
}

__global__ void knn_search(int* __restrict__ idx_out) {
    const int p = blockIdx.x * 64 + threadIdx.x;
    if (p >= N_SPOTS) return;
    const float4 me = g_sp4[p];
    const int i = __float_as_int(me.z);
    const float sqi = __fadd_rn(__fmul_rn(me.x, me.x), __fmul_rn(me.y, me.y));
    const int cx = cell_x(me.x), cy = cell_x(me.y);

    float dd[KNN_K]; int jj[KNN_K];
#pragma unroll
    for (int k = 0; k < KNN_K; k++) { dd[k] = INF_F; jj[k] = 0x7fffffff; }
    float wd = INF_F; int wj = 0x7fffffff; int ws = 0;

    for (int R = 0; R <= GRID_D; R++) {
        if (R >= 2) {
            const float b = (float)(R - 1) * CSZ;
            if (wd + SLACK < b * b) break;
        }
        const int x0 = max(0, cx - R), x1 = min(GRID_D - 1, cx + R);
        const int y0 = max(0, cy - R), y1 = min(GRID_D - 1, cy + R);
        for (int yy = y0; yy <= y1; yy++) {
            if (yy == cy - R || yy == cy + R) {
                for (int xx = x0; xx <= x1; xx++)
                    proc_cell(yy * GRID_D + xx, i, me.x, me.y, sqi, dd, jj, wd, wj, ws);
            } else {
                if (cx - R >= 0)     proc_cell(yy * GRID_D + cx - R, i, me.x, me.y, sqi, dd, jj, wd, wj, ws);
                if (cx + R < GRID_D) proc_cell(yy * GRID_D + cx + R, i, me.x, me.y, sqi, dd, jj, wd, wj, ws);
            }
        }
    }
#pragma unroll
    for (int k = 0; k < KNN_K; k++) idx_out[i * KNN_K + k] = jj[k];
}

// --------------------------- aggregation (+ z bf16 split) ----------------------
__global__ void agg_kernel(const float* __restrict__ x,
                           const float* __restrict__ xn,
                           float* __restrict__ z_out,
                           float* __restrict__ hr_out) {
    const int i   = blockIdx.x;
    const int tid = threadIdx.x;          // 0..127
    const int lane = tid & 31, wrp = tid >> 5;

    __shared__ int   nb[KNN_K];
    __shared__ float red[4][KNN_K];
    __shared__ float neg_mean[KNN_K];

    if (tid < KNN_K) nb[tid] = g_idx[i * KNN_K + tid];
    __syncthreads();

    const float xi = x[(size_t)i * D_LAT + tid];
    float xv[KNN_K];
    float fd[KNN_K];
#pragma unroll
    for (int k = 0; k < KNN_K; k++) {
        const float v = x[(size_t)nb[k] * D_LAT + tid];
        xv[k] = v;
        const float d = v - xi;
        fd[k] = d * d;
    }
#pragma unroll
    for (int k = 0; k < KNN_K; k++) {
        float v = fd[k];
#pragma unroll
        for (int o = 16; o > 0; o >>= 1) v += __shfl_xor_sync(0xffffffffu, v, o);
        if (lane == 0) red[wrp][k] = v;
    }
    __syncthreads();
    if (tid < KNN_K) {
        const float s = red[0][tid] + red[1][tid] + red[2][tid] + red[3][tid];
        neg_mean[tid] = -(s * (1.0f / 128.0f));
    }
    __syncthreads();

    float m = neg_mean[0];
#pragma unroll
    for (int k = 1; k < KNN_K; k++) m = fmaxf(m, neg_mean[k]);
    float e[KNN_K], se = 0.0f;
#pragma unroll
    for (int k = 0; k < KNN_K; k++) { e[k] = expf(neg_mean[k] - m); se += e[k]; }
    float w[KNN_K];
#pragma unroll
    for (int k = 0; k < KNN_K; k++) w[k] = e[k] / se;

    float acc = 0.0f;
#pragma unroll
    for (int k = 0; k < KNN_K; k++) acc = __fmaf_rn(w[k], xv[k], acc);
    z_out[(size_t)i * D_LAT + tid] = acc;

    // bf16 hi/lo split of z, packed per k-pair (even lane packs tid & tid+1)
    const float accn = __shfl_down_sync(0xffffffffu, acc, 1);
    if ((tid & 1) == 0) {
        __nv_bfloat16 h0, l0, h1, l1;
        split_bf(acc,  h0, l0);
        split_bf(accn, h1, l1);
        g_zh[(size_t)i * 64 + (tid >> 1)] = pack2(h0, h1);
        g_zl[(size_t)i * 64 + (tid >> 1)] = pack2(l0, l1);
    }

#pragma unroll
    for (int s = 0; s < SCALE; s++) {
        float a = 0.0f;
#pragma unroll
        for (int k = 0; k < KNN_K; k++)
            a = __fmaf_rn(w[k], xn[((size_t)s * N_SPOTS + nb[k]) * D_LAT + tid], a);
        hr_out[(size_t)i * (SCALE * D_LAT) + s * D_LAT + tid] = a;
    }
}

// --------------------------- W bf16 split --------------------------------------
__global__ void split_w(const float* __restrict__ W) {
    const int idx = blockIdx.x * 256 + threadIdx.x;     // kp * D_IN + n
    if (idx >= 64 * D_IN) return;
    const int kp = idx / D_IN, n = idx - kp * D_IN;
    const float v0 = W[(size_t)(2 * kp)     * D_IN + n];
    const float v1 = W[(size_t)(2 * kp + 1) * D_IN + n];
    __nv_bfloat16 h0, l0, h1, l1;
    split_bf(v0, h0, l0);
    split_bf(v1, h1, l1);
    g_bh[idx] = pack2(h0, h1);
    g_bl[idx] = pack2(l0, l1);
}

// --------------------------- Gram: G = Z^T Z, s = colsum(Z) --------------------
#define GRAM_BLOCKS 80
__global__ void __launch_bounds__(256) gram_kernel(const float* __restrict__ z) {
    __shared__ float zrow[D_LAT];
    const int tid = threadIdx.x;
    const int i_own = tid >> 1;           // G row this thread owns
    const int jb    = (tid & 1) * 64;     // half of the columns

    float acc[64];
#pragma unroll
    for (int q = 0; q < 64; q++) acc[q] = 0.0f;
    float s_loc = 0.0f;

    for (int m = blockIdx.x; m < N_SPOTS; m += GRAM_BLOCKS) {
        if (tid < D_LAT) zrow[tid] = z[(size_t)m * D_LAT + tid];
        __syncthreads();
        const float zi = zrow[i_own];
#pragma unroll
        for (int q = 0; q < 64; q++) acc[q] = __fmaf_rn(zi, zrow[jb + q], acc[q]);
        if (tid < D_LAT) s_loc += zrow[tid];
        __syncthreads();
    }
#pragma unroll
    for (int q = 0; q < 64; q++) atomicAdd(&g_G[i_own * D_LAT + jb + q], acc[q]);
    if (tid < D_LAT) atomicAdd(&g_s[tid], s_loc);
}

// --------------------------- BN stats from Gram --------------------------------
__global__ void __launch_bounds__(256) stats_kernel(const float* __restrict__ W,
                                                    const float* __restrict__ bias) {
    __shared__ float Gs[D_LAT][65];   // half of G (padded)
    __shared__ float ws[8][D_LAT];
    __shared__ float ss[D_LAT];

    const int tid = threadIdx.x;
    const int wrp = tid >> 5, lane = tid & 31;
    const int c0 = blockIdx.x * 8;
    const int c  = c0 + wrp;

    for (int idx = tid; idx < 8 * D_LAT; idx += 256) {
        const int cc = idx & 7, i = idx >> 3;
        ws[cc][i] = W[(size_t)i * D_IN + c0 + cc];
    }
    if (tid < D_LAT) ss[tid] = g_s[tid];

    float tpart[4] = {0.0f, 0.0f, 0.0f, 0.0f};
    for (int half = 0; half < 2; half++) {
        __syncthreads();
        for (int idx = tid; idx < D_LAT * 64; idx += 256) {
            const int i = idx >> 6, jj = idx & 63;
            Gs[i][jj] = g_G[i * D_LAT + half * 64 + jj];
        }
        __syncthreads();
#pragma unroll
        for (int ii = 0; ii < 4; ii++) {
            const int i = lane + ii * 32;
            float t = tpart[ii];
            const float* wr = &ws[wrp][half * 64];
#pragma unroll
            for (int jj = 0; jj < 64; jj++) t = __fmaf_rn(Gs[i][jj], wr[jj], t);
            tpart[ii] = t;
        }
    }

    float u = 0.0f, sw = 0.0f;
#pragma unroll
    for (int ii = 0; ii < 4; ii++) {
        const int i = lane + ii * 32;
        const float wi = ws[wrp][i];
        u  = __fmaf_rn(wi, tpart[ii], u);
        sw = __fmaf_rn(ss[i], wi, sw);
    }
#pragma unroll
    for (int o = 16; o > 0; o >>= 1) {
        u  += __shfl_xor_sync(0xffffffffu, u, o);
        sw += __shfl_xor_sync(0xffffffffu, sw, o);
    }
    if (lane == 0) {
        const float b   = bias[c];
        const float mu  = sw * (1.0f / (float)N_SPOTS) + b;
        const float eh2 = (u + 2.0f * b * sw) * (1.0f / (float)N_SPOTS) + b * b;
        const float var = eh2 - mu * mu;
        g_mu[c] = mu;
        g_rs[c] = 1.0f / sqrtf(var + BN_EPS);
    }
}

// ------------------------------ GEMM (3x bf16 tensor cores) --------------------
// de_feat = ELU(BN(z @ W + b))  [10000 x 3000], K=128.
// Operands pre-split into bf16 hi/lo (packed kpairs) — no conversion in-loop.
// Block tile 128x128, k-slab 16, double buffered. Warp tile 32x64.
// Epilogue: bias + BN (mu/rs precomputed via Gram) + ELU, write de_out directly.

__device__ __forceinline__ void mma_bf16(float* d, const uint32_t* a, const uint32_t* b) {
    asm volatile(
        "mma.sync.aligned.m16n8k16.row.col.f32.bf16.bf16.f32 "
        "{%0,%1,%2,%3}, {%4,%5,%6,%7}, {%8,%9}, {%0,%1,%2,%3};"
        : "+f"(d[0]), "+f"(d[1]), "+f"(d[2]), "+f"(d[3])
        : "r"(a[0]), "r"(a[1]), "r"(a[2]), "r"(a[3]), "r"(b[0]), "r"(b[1]));
}

#define GM 128
#define GN 128
#define GK 16
#define ASTR 20    // uint32 per A row: words 0..7 hi (kpairs), 8..15 lo, 4 pad
#define BSTR 136   // uint32 per B kpair row: 128 n + 8 pad

__global__ void __launch_bounds__(256) gemm_kernel(const float* __restrict__ bias,
                                                   const float* __restrict__ gamma,
                                                   const float* __restrict__ beta,
                                                   float* __restrict__ de_out) {
    __shared__ __align__(16) uint32_t As[2][GM][ASTR];   // [buf][m][kpair(hi:0-7, lo:8-15)]
    __shared__ __align__(16) uint32_t Bs[2][16][BSTR];   // [buf][kpair(hi:0-7, lo:8-15)][n]

    const int bm  = blockIdx.y * GM;
    const int bn  = blockIdx.x * GN;
    const int tid = threadIdx.x;
    const int lane = tid & 31;
    const int wrp  = tid >> 5;
    const int tg   = lane & 3;     // threadID in quad
    const int gp   = lane >> 2;    // groupID
    const int m0w  = (wrp & 3) * 32;   // warp row offset in tile
    const int n0w  = (wrp >> 2) * 64;  // warp col offset in tile

    // --- global load indices ---
    const int arow_l = tid & 127;       // A row within tile
    const int ahalf  = tid >> 7;        // kpairs 0..3 or 4..7 of slab
    const int arow   = min(bm + arow_l, N_SPOTS - 1);
    const int bkp    = tid >> 5;        // B kpair within slab (0..7)
    const int bn4    = (tid & 31) * 4;  // B col within tile
    const int bcol   = min(bn + bn4, D_IN - 4);

    const uint32_t* zh_row = g_zh + (size_t)arow * 64;
    const uint32_t* zl_row = g_zl + (size_t)arow * 64;

    uint4 rah, ral, rbh, rbl;
    rah = *(const uint4*)&zh_row[ahalf * 4];
    ral = *(const uint4*)&zl_row[ahalf * 4];
    rbh = *(const uint4*)&g_bh[(size_t)bkp * D_IN + bcol];
    rbl = *(const uint4*)&g_bl[(size_t)bkp * D_IN + bcol];

    float acc[2][8][4];
#pragma unroll
    for (int mt = 0; mt < 2; mt++)
#pragma unroll
        for (int nt = 0; nt < 8; nt++)
#pragma unroll
            for (int q = 0; q < 4; q++) acc[mt][nt][q] = 0.0f;

#define STS_AB(buf)                                          \
    {                                                        \
        *(uint4*)&As[buf][arow_l][ahalf * 4]     = rah;      \
        *(uint4*)&As[buf][arow_l][8 + ahalf * 4] = ral;      \
        *(uint4*)&Bs[buf][bkp][bn4]              = rbh;      \
        *(uint4*)&Bs[buf][8 + bkp][bn4]          = rbl;      \
    }

    STS_AB(0);
    __syncthreads();

#pragma unroll 1
    for (int s = 0; s < D_LAT / GK; s++) {
        if (s < D_LAT / GK - 1) {
            const int kp0 = (s + 1) * 8;     // kpair base of next slab
            rah = *(const uint4*)&zh_row[kp0 + ahalf * 4];
            ral = *(const uint4*)&zl_row[kp0 + ahalf * 4];
            rbh = *(const uint4*)&g_bh[(size_t)(kp0 + bkp) * D_IN + bcol];
            rbl = *(const uint4*)&g_bl[(size_t)(kp0 + bkp) * D_IN + bcol];
        }
        const int cur = s & 1;

        uint32_t ah[2][4], al[2][4];
#pragma unroll
        for (int mt = 0; mt < 2; mt++) {
            const int mr = m0w + mt * 16;
            ah[mt][0] = As[cur][mr + gp][tg];
            ah[mt][1] = As[cur][mr + gp + 8][tg];
            ah[mt][2] = As[cur][mr + gp][tg + 4];
            ah[mt][3] = As[cur][mr + gp + 8][tg + 4];
            al[mt][0] = As[cur][mr + gp][8 + tg];
            al[mt][1] = As[cur][mr + gp + 8][8 + tg];
            al[mt][2] = As[cur][mr + gp][8 + tg + 4];
            al[mt][3] = As[cur][mr + gp + 8][8 + tg + 4];
        }

#pragma unroll
        for (int nt = 0; nt < 8; nt++) {
            const int nc = n0w + nt * 8 + gp;
            uint32_t bh[2] = { Bs[cur][tg][nc],     Bs[cur][tg + 4][nc] };
            uint32_t bl[2] = { Bs[cur][8 + tg][nc], Bs[cur][8 + tg + 4][nc] };
#pragma unroll
            for (int mt = 0; mt < 2; mt++) {
                mma_bf16(acc[mt][nt], ah[mt], bh);   // hi*hi
                mma_bf16(acc[mt][nt], ah[mt], bl);   // hi*lo
                mma_bf16(acc[mt][nt], al[mt], bh);   // lo*hi
            }
        }

        if (s < D_LAT / GK - 1) {
            STS_AB((s + 1) & 1);
            __syncthreads();
        }
    }

    // ---- epilogue: bias + BN + ELU, write de_out directly ----
#pragma unroll
    for (int nt = 0; nt < 8; nt++) {
        const int col = bn + n0w + nt * 8 + tg * 2;
        if (col >= D_IN) continue;          // col even, D_IN even -> col+1 also valid
        const float bia0 = __ldg(&bias[col]),  bia1 = __ldg(&bias[col + 1]);
        const float mu0  = g_mu[col],          mu1  = g_mu[col + 1];
        const float rs0  = g_rs[col],          rs1  = g_rs[col + 1];
        const float ga0  = __ldg(&gamma[col]), ga1  = __ldg(&gamma[col + 1]);
        const float be0  = __ldg(&beta[col]),  be1  = __ldg(&beta[col + 1]);
#pragma unroll
        for (int mt = 0; mt < 2; mt++) {
#pragma unroll
            for (int hf = 0; hf < 2; hf++) {
                const int row = bm + m0w + mt * 16 + gp + hf * 8;
                if (row >= N_SPOTS) continue;
                const float h0 = acc[mt][nt][hf * 2 + 0] + bia0;
                const float h1 = acc[mt][nt][hf * 2 + 1] + bia1;
                float y0 = (h0 - mu0) * rs0 * ga0 + be0;
                float y1 = (h1 - mu1) * rs1 * ga1 + be1;
                y0 = (y0 > 0.0f) ? y0 : expm1f(y0);
                y1 = (y1 > 0.0f) ? y1 : expm1f(y1);
                *(float2*)&de_out[(size_t)row * D_IN + col] = make_float2(y0, y1);
            }
        }
    }
}

// ------------------------------- launch ----------------------------------------
extern "C" void kernel_launch(void* const* d_in, const int* in_sizes, int n_in,
                              void* d_out, int out_size) {
    const float* x     = (const float*)d_in[0];   // [10000,128]
    const float* xn    = (const float*)d_in[1];   // [60000,128]
    const float* sp    = (const float*)d_in[2];   // [10000,2]
    const float* W     = (const float*)d_in[3];   // [128,3000]
    const float* bias  = (const float*)d_in[4];   // [3000]
    const float* gamma = (const float*)d_in[5];   // [3000]
    const float* beta  = (const float*)d_in[6];   // [3000]

    float* out = (float*)d_out;
    float* z_out  = out;                                   // [10000,128]
    float* de_out = out + (size_t)N_SPOTS * D_LAT;         // [10000,3000]
    float* hr_out = de_out + (size_t)N_SPOTS * D_IN;       // [10000,768]

    int* idx_ptr;   cudaGetSymbolAddress((void**)&idx_ptr, g_idx);
    void *cnt_p, *cur_p, *G_p, *s_p;
    cudaGetSymbolAddress(&cnt_p, g_cnt);
    cudaGetSymbolAddress(&cur_p, g_cur);
    cudaGetSymbolAddress(&G_p,   g_G);
    cudaGetSymbolAddress(&s_p,   g_s);

    cudaMemsetAsync(cnt_p, 0, NCELLS * sizeof(int));
    cudaMemsetAsync(cur_p, 0, NCELLS * sizeof(int));
    cudaMemsetAsync(G_p,   0, D_LAT * D_LAT * sizeof(float));
    cudaMemsetAsync(s_p,   0, D_LAT * sizeof(float));

    split_w    <<<(64 * D_IN + 255) / 256, 256>>>(W);
    knn_count  <<<(N_SPOTS + 255) / 256, 256>>>((const float2*)sp);
    knn_scan   <<<1, 32>>>();
    knn_scatter<<<(N_SPOTS + 255) / 256, 256>>>((const float2*)sp);
    knn_search <<<(N_SPOTS + 63) / 64, 64>>>(idx_ptr);
    agg_kernel <<<N_SPOTS, 128>>>(x, xn, z_out, hr_out);
    gram_kernel<<<GRAM_BLOCKS, 256>>>(z_out);
    stats_kernel<<<D_IN / 8, 256>>>(W, bias);
    gemm_kernel<<<dim3((D_IN + GN - 1) / GN, (N_SPOTS + GM - 1) / GM), 256>>>(
        bias, gamma, beta, de_out);
}